// round 1
// baseline (speedup 1.0000x reference)
#include <cuda_runtime.h>
#include <math.h>

#define DM 1024
#define BSZ 2
#define SL  2048
#define NH  16
#define DKH 64
#define MR  (BSZ*SL)   // 4096 rows for projection GEMMs

// Scratch (device globals: allocation-free per harness rules)
__device__ float g_q [MR*DM];
__device__ float g_k [MR*DM];
__device__ float g_v [MR*DM];
__device__ float g_ao[MR*DM];

// ---------------------------------------------------------------------------
// C[4096,1024] = A[4096,1024] @ W[1024,1024] + bias
// 128x128 block tile, BK=16, 256 threads, 8x8 per-thread tile.
// ---------------------------------------------------------------------------
__global__ __launch_bounds__(256) void gemm_bias_kernel(
    const float* __restrict__ A, const float* __restrict__ W,
    const float* __restrict__ bias, float* __restrict__ C)
{
    __shared__ float AsT[16*128];   // AsT[k][m]
    __shared__ float Bs [16*128];   // Bs [k][n]

    const int tid = threadIdx.x;
    const int tx  = tid & 15;       // n-tile index
    const int ty  = tid >> 4;       // m-tile index
    const int bm  = blockIdx.x;     // 0..31
    const int bn  = blockIdx.y;     // 0..7

    const float* Ablk = A + bm*128*DM;
    const float* Wblk = W + bn*128;

    float acc[8][8];
#pragma unroll
    for (int i = 0; i < 8; ++i)
#pragma unroll
        for (int j = 0; j < 8; ++j) acc[i][j] = 0.f;

    const int a_row = tid >> 1;          // 0..127
    const int a_k   = (tid & 1) * 4;     // 0 or 4
    const int b_row = tid >> 5;          // 0..7
    const int b_col = (tid & 31) * 4;    // 0..124

    for (int kb = 0; kb < DM; kb += 16) {
        float4 a0 = *(const float4*)(Ablk + a_row*DM + kb + a_k);
        float4 a1 = *(const float4*)(Ablk + a_row*DM + kb + a_k + 8);
        float4 b0 = *(const float4*)(Wblk + (kb + b_row    )*DM + b_col);
        float4 b1 = *(const float4*)(Wblk + (kb + b_row + 8)*DM + b_col);
        __syncthreads();
        AsT[(a_k+0)*128 + a_row] = a0.x;
        AsT[(a_k+1)*128 + a_row] = a0.y;
        AsT[(a_k+2)*128 + a_row] = a0.z;
        AsT[(a_k+3)*128 + a_row] = a0.w;
        AsT[(a_k+8)*128 + a_row] = a1.x;
        AsT[(a_k+9)*128 + a_row] = a1.y;
        AsT[(a_k+10)*128 + a_row] = a1.z;
        AsT[(a_k+11)*128 + a_row] = a1.w;
        *(float4*)(Bs + (b_row    )*128 + b_col) = b0;
        *(float4*)(Bs + (b_row + 8)*128 + b_col) = b1;
        __syncthreads();
#pragma unroll
        for (int k = 0; k < 16; ++k) {
            float a[8], b[8];
            *(float4*)(a)   = *(const float4*)(AsT + k*128 + ty*8);
            *(float4*)(a+4) = *(const float4*)(AsT + k*128 + ty*8 + 4);
            *(float4*)(b)   = *(const float4*)(Bs  + k*128 + tx*8);
            *(float4*)(b+4) = *(const float4*)(Bs  + k*128 + tx*8 + 4);
#pragma unroll
            for (int i = 0; i < 8; ++i)
#pragma unroll
                for (int j = 0; j < 8; ++j)
                    acc[i][j] += a[i] * b[j];
        }
    }

    const int row0 = bm*128 + ty*8;
    const int col0 = bn*128 + tx*8;
    float bv[8];
#pragma unroll
    for (int j = 0; j < 8; ++j) bv[j] = bias[col0 + j];
#pragma unroll
    for (int i = 0; i < 8; ++i) {
        float4 o0, o1;
        o0.x = acc[i][0]+bv[0]; o0.y = acc[i][1]+bv[1];
        o0.z = acc[i][2]+bv[2]; o0.w = acc[i][3]+bv[3];
        o1.x = acc[i][4]+bv[4]; o1.y = acc[i][5]+bv[5];
        o1.z = acc[i][6]+bv[6]; o1.w = acc[i][7]+bv[7];
        *(float4*)(C + (row0+i)*DM + col0)     = o0;
        *(float4*)(C + (row0+i)*DM + col0 + 4) = o1;
    }
}

// ---------------------------------------------------------------------------
// Flash attention (fp32). grid = (S/64 q-tiles, H*B). block = 256 threads.
// Per iteration: 64 keys. Smem tiles (exactly 48KB):
//   QsT : transposed Q, group-swizzled:  QsT[d*64 + 4*((m>>2)^(d&15)) + (m&3)]
//   KPs : K transposed/swizzled, then reused for P (kk-major, same swizzle)
//   Vs  : natural [kk][d]
// Swizzle makes every transposed store conflict-free and every read either a
// broadcast or a conflict-free float4.
// ---------------------------------------------------------------------------
__global__ __launch_bounds__(256) void attn_kernel(
    const float* __restrict__ Qp, const float* __restrict__ Kp,
    const float* __restrict__ Vp, float* __restrict__ Ao)
{
    __shared__ float QsT[64*64];
    __shared__ float KPs[64*64];
    __shared__ float Vs [64*64];

    const int tid = threadIdx.x;
    const int tx  = tid & 15;          // score col group / out d group
    const int ty  = tid >> 4;          // row group (4 rows)
    const int qblk = blockIdx.x;       // 0..31
    const int hb   = blockIdx.y;       // 0..31 : h = hb>>1, b = hb&1
    const int b    = hb & 1;
    const int h    = hb >> 1;
    const int base = b*SL*DM + h*64;   // row-major [B*S, D] column slice
    const int q0   = qblk * 64;

    const int l_dg  = tid & 15;        // d-group for gmem loader (coalesced)
    const int l_row = tid >> 4;        // row 0..15 (+16*r)

    // ---- Load Q tile, pre-scaled by 1/sqrt(dk) = 0.125 -------------------
#pragma unroll
    for (int r = 0; r < 4; ++r) {
        const int m = l_row + r*16;
        const int d = l_dg * 4;
        float4 v4 = *(const float4*)(Qp + base + (q0+m)*DM + d);
        v4.x *= 0.125f; v4.y *= 0.125f; v4.z *= 0.125f; v4.w *= 0.125f;
        QsT[(d+0)*64 + 4*((m>>2) ^ ((d+0)&15)) + (m&3)] = v4.x;
        QsT[(d+1)*64 + 4*((m>>2) ^ ((d+1)&15)) + (m&3)] = v4.y;
        QsT[(d+2)*64 + 4*((m>>2) ^ ((d+2)&15)) + (m&3)] = v4.z;
        QsT[(d+3)*64 + 4*((m>>2) ^ ((d+3)&15)) + (m&3)] = v4.w;
    }

    float acc[4][4];
#pragma unroll
    for (int i = 0; i < 4; ++i)
#pragma unroll
        for (int j = 0; j < 4; ++j) acc[i][j] = 0.f;
    float mrow[4] = {-INFINITY, -INFINITY, -INFINITY, -INFINITY};
    float lrow[4] = {0.f, 0.f, 0.f, 0.f};

    for (int it = 0; it < SL/64; ++it) {
        const int k0 = it * 64;
        __syncthreads();   // prior P@V finished reading KPs / Vs
        // ---- Load K (transposed+swizzled) and V (natural) ----------------
#pragma unroll
        for (int r = 0; r < 4; ++r) {
            const int n = l_row + r*16;
            const int d = l_dg * 4;
            float4 kv = *(const float4*)(Kp + base + (k0+n)*DM + d);
            float4 vv = *(const float4*)(Vp + base + (k0+n)*DM + d);
            KPs[(d+0)*64 + 4*((n>>2) ^ ((d+0)&15)) + (n&3)] = kv.x;
            KPs[(d+1)*64 + 4*((n>>2) ^ ((d+1)&15)) + (n&3)] = kv.y;
            KPs[(d+2)*64 + 4*((n>>2) ^ ((d+2)&15)) + (n&3)] = kv.z;
            KPs[(d+3)*64 + 4*((n>>2) ^ ((d+3)&15)) + (n&3)] = kv.w;
            *(float4*)(Vs + n*64 + d) = vv;
        }
        __syncthreads();

        // ---- Scores S = (Q/8) @ K^T : 64x64 tile, 4x4 per thread ---------
        float s[4][4];
#pragma unroll
        for (int i = 0; i < 4; ++i)
#pragma unroll
            for (int j = 0; j < 4; ++j) s[i][j] = 0.f;
#pragma unroll 8
        for (int d = 0; d < 64; ++d) {
            const float4 qv = *(const float4*)(QsT + d*64 + 4*(ty ^ (d & 15)));
            const float4 kv = *(const float4*)(KPs + d*64 + 4*(tx ^ (d & 15)));
            const float qa[4] = {qv.x, qv.y, qv.z, qv.w};
            const float ka[4] = {kv.x, kv.y, kv.z, kv.w};
#pragma unroll
            for (int i = 0; i < 4; ++i)
#pragma unroll
                for (int j = 0; j < 4; ++j)
                    s[i][j] += qa[i] * ka[j];
        }

        // ---- Online softmax (rows owned by the 16 tx-lanes of this ty) ---
        float mx[4];
#pragma unroll
        for (int i = 0; i < 4; ++i)
            mx[i] = fmaxf(fmaxf(s[i][0], s[i][1]), fmaxf(s[i][2], s[i][3]));
#pragma unroll
        for (int off = 8; off >= 1; off >>= 1)
#pragma unroll
            for (int i = 0; i < 4; ++i)
                mx[i] = fmaxf(mx[i], __shfl_xor_sync(0xffffffffu, mx[i], off));

        float corr[4], rs[4];
#pragma unroll
        for (int i = 0; i < 4; ++i) {
            const float mnew = fmaxf(mrow[i], mx[i]);
            corr[i] = __expf(mrow[i] - mnew);
            mrow[i] = mnew;
            float r = 0.f;
#pragma unroll
            for (int j = 0; j < 4; ++j) {
                s[i][j] = __expf(s[i][j] - mnew);
                r += s[i][j];
            }
            rs[i] = r;
        }
#pragma unroll
        for (int off = 8; off >= 1; off >>= 1)
#pragma unroll
            for (int i = 0; i < 4; ++i)
                rs[i] += __shfl_xor_sync(0xffffffffu, rs[i], off);
#pragma unroll
        for (int i = 0; i < 4; ++i) {
            lrow[i] = lrow[i] * corr[i] + rs[i];
#pragma unroll
            for (int j = 0; j < 4; ++j) acc[i][j] *= corr[i];
        }

        __syncthreads();   // all threads done reading K from KPs
        // ---- Write P into KPs (kk-major, same group swizzle) -------------
#pragma unroll
        for (int j = 0; j < 4; ++j) {
            const int n = 4*tx + j;
            float* dst = KPs + n*64 + 4*(ty ^ (n & 15));
#pragma unroll
            for (int i = 0; i < 4; ++i) dst[i] = s[i][j];
        }
        __syncthreads();

        // ---- O += P @ V --------------------------------------------------
#pragma unroll 8
        for (int kk = 0; kk < 64; ++kk) {
            const float4 pv = *(const float4*)(KPs + kk*64 + 4*(ty ^ (kk & 15)));
            const float4 vv = *(const float4*)(Vs  + kk*64 + 4*tx);
            const float pa[4] = {pv.x, pv.y, pv.z, pv.w};
            const float va[4] = {vv.x, vv.y, vv.z, vv.w};
#pragma unroll
            for (int i = 0; i < 4; ++i)
#pragma unroll
                for (int j = 0; j < 4; ++j)
                    acc[i][j] += pa[i] * va[j];
        }
    }

    // ---- Epilogue: O /= l, write column slice ----------------------------
#pragma unroll
    for (int i = 0; i < 4; ++i) {
        const float inv = 1.f / lrow[i];
        float4 o;
        o.x = acc[i][0]*inv; o.y = acc[i][1]*inv;
        o.z = acc[i][2]*inv; o.w = acc[i][3]*inv;
        *(float4*)(Ao + base + (q0 + 4*ty + i)*DM + 4*tx) = o;
    }
}

// ---------------------------------------------------------------------------
extern "C" void kernel_launch(void* const* d_in, const int* in_sizes, int n_in,
                              void* d_out, int out_size)
{
    const float* q   = (const float*)d_in[0];
    const float* k   = (const float*)d_in[1];
    const float* v   = (const float*)d_in[2];
    const float* w_q = (const float*)d_in[3];
    const float* b_q = (const float*)d_in[4];
    const float* w_k = (const float*)d_in[5];
    const float* b_k = (const float*)d_in[6];
    const float* w_v = (const float*)d_in[7];
    const float* b_v = (const float*)d_in[8];
    const float* w_o = (const float*)d_in[9];
    const float* b_o = (const float*)d_in[10];
    float* out = (float*)d_out;

    float *gq, *gk, *gv, *gao;
    cudaGetSymbolAddress((void**)&gq,  g_q);
    cudaGetSymbolAddress((void**)&gk,  g_k);
    cudaGetSymbolAddress((void**)&gv,  g_v);
    cudaGetSymbolAddress((void**)&gao, g_ao);

    const dim3 blk(256);
    const dim3 gproj(MR/128, DM/128);        // (32, 8)
    gemm_bias_kernel<<<gproj, blk>>>(q, w_q, b_q, gq);
    gemm_bias_kernel<<<gproj, blk>>>(k, w_k, b_k, gk);
    gemm_bias_kernel<<<gproj, blk>>>(v, w_v, b_v, gv);
    attn_kernel<<<dim3(SL/64, NH*BSZ), blk>>>(gq, gk, gv, gao);
    gemm_bias_kernel<<<gproj, blk>>>(gao, w_o, b_o, out);
}

// round 3
// speedup vs baseline: 1.2710x; 1.2710x over previous
#include <cuda_runtime.h>
#include <cuda_bf16.h>
#include <math.h>
#include <stdint.h>

#define DM 1024
#define BSZ 2
#define SL  2048
#define NH  16
#define MR  (BSZ*SL)   // 4096 rows for projection GEMMs

// ---------------------------------------------------------------------------
// Scratch (device globals: allocation-free per harness rules)
// ---------------------------------------------------------------------------
__device__ float g_q [MR*DM];
__device__ float g_k [MR*DM];
__device__ float g_v [MR*DM];
__device__ float g_ao[MR*DM];

__device__ __nv_bfloat16 g_qh[MR*DM], g_ql[MR*DM];
__device__ __nv_bfloat16 g_kh[MR*DM], g_kl[MR*DM];
__device__ __nv_bfloat16 g_vh[MR*DM], g_vl[MR*DM];
__device__ __nv_bfloat16 g_aoh[MR*DM], g_aol[MR*DM];
__device__ __nv_bfloat16 g_wqh[DM*DM], g_wql[DM*DM];
__device__ __nv_bfloat16 g_wkh[DM*DM], g_wkl[DM*DM];
__device__ __nv_bfloat16 g_wvh[DM*DM], g_wvl[DM*DM];
__device__ __nv_bfloat16 g_woh[DM*DM], g_wol[DM*DM];

// ---------------------------------------------------------------------------
// Helpers (family-portable PTX only: cp.async, ldmatrix, mma.sync)
// ---------------------------------------------------------------------------
__device__ __forceinline__ uint32_t smem_u32(const void* p) {
    uint32_t a;
    asm("{ .reg .u64 t; cvta.to.shared.u64 t, %1; cvt.u32.u64 %0, t; }"
        : "=r"(a) : "l"(p));
    return a;
}
__device__ __forceinline__ void cpa16(uint32_t dst, const void* src) {
    asm volatile("cp.async.cg.shared.global [%0], [%1], 16;" :: "r"(dst), "l"(src));
}
__device__ __forceinline__ void ldsm4(uint32_t* r, uint32_t addr) {
    asm volatile("ldmatrix.sync.aligned.m8n8.x4.shared.b16 {%0,%1,%2,%3}, [%4];"
        : "=r"(r[0]), "=r"(r[1]), "=r"(r[2]), "=r"(r[3]) : "r"(addr));
}
__device__ __forceinline__ void mma16816(float* c, const uint32_t* a, const uint32_t* b) {
    asm volatile("mma.sync.aligned.m16n8k16.row.col.f32.bf16.bf16.f32 "
        "{%0,%1,%2,%3}, {%4,%5,%6,%7}, {%8,%9}, {%0,%1,%2,%3};"
        : "+f"(c[0]), "+f"(c[1]), "+f"(c[2]), "+f"(c[3])
        : "r"(a[0]), "r"(a[1]), "r"(a[2]), "r"(a[3]), "r"(b[0]), "r"(b[1]));
}

// ---------------------------------------------------------------------------
// Split conversion kernels (fp32 -> hi/lo bf16)
// ---------------------------------------------------------------------------
__global__ void split2_kernel(const float* __restrict__ x,
                              __nv_bfloat162* __restrict__ h,
                              __nv_bfloat162* __restrict__ l, int n2)
{
    int i = blockIdx.x * blockDim.x + threadIdx.x;
    if (i < n2) {
        float2 v = ((const float2*)x)[i];
        __nv_bfloat16 h0 = __float2bfloat16(v.x);
        __nv_bfloat16 h1 = __float2bfloat16(v.y);
        __nv_bfloat16 l0 = __float2bfloat16(v.x - __bfloat162float(h0));
        __nv_bfloat16 l1 = __float2bfloat16(v.y - __bfloat162float(h1));
        h[i] = __halves2bfloat162(h0, h1);
        l[i] = __halves2bfloat162(l0, l1);
    }
}

// Transpose + split: W[k][n] (1024x1024 fp32) -> hT/lT[n][k] bf16
__global__ void tsplit_kernel(const float* __restrict__ W,
                              __nv_bfloat16* __restrict__ hT,
                              __nv_bfloat16* __restrict__ lT)
{
    __shared__ float t[32][33];
    const int tx = threadIdx.x, ty = threadIdx.y;   // 32 x 8
    const int n0 = blockIdx.x * 32, k0 = blockIdx.y * 32;
#pragma unroll
    for (int r = 0; r < 4; ++r)
        t[ty + 8*r][tx] = W[(k0 + ty + 8*r) * DM + n0 + tx];
    __syncthreads();
#pragma unroll
    for (int r = 0; r < 4; ++r) {
        const int n = n0 + ty + 8*r;
        const float v = t[tx][ty + 8*r];
        __nv_bfloat16 h = __float2bfloat16(v);
        __nv_bfloat16 l = __float2bfloat16(v - __bfloat162float(h));
        hT[n * DM + k0 + tx] = h;
        lT[n * DM + k0 + tx] = l;
    }
}

// ---------------------------------------------------------------------------
// mma.sync bf16x3 GEMM: C[4096,1024] = (Ah+Al) @ (Wh+Wl) + bias
//   Block 128x128, BK=32, 256 threads (8 warps as 4m x 2n), warp tile 32x64.
//   Smem rows padded to 80B -> conflict-free ldmatrix phases.
//   3 MMAs per (mt,nt,k16): Ah*Bh + Ah*Bl + Al*Bh.
// ---------------------------------------------------------------------------
#define BK 32
#define RS 40                       // smem row stride in bf16 elems (80B)
#define TILE_BYTES (128*RS*2)       // 10240
#define STAGE_BYTES (4*TILE_BYTES)  // Ah, Al, Bh, Bl = 40960
#define GEMM_SMEM (2*STAGE_BYTES)   // 81920
#define NCHUNK (DM/BK)              // 32

__global__ __launch_bounds__(256) void gemm_mma_kernel(
    const __nv_bfloat16* __restrict__ Ahp, const __nv_bfloat16* __restrict__ Alp,
    const __nv_bfloat16* __restrict__ BhT, const __nv_bfloat16* __restrict__ BlT,
    const float* __restrict__ bias, float* __restrict__ C)
{
    extern __shared__ char smem[];
    const uint32_t sbase = smem_u32(smem);
    const int tid  = threadIdx.x;
    const int wid  = tid >> 5;
    const int lane = tid & 31;
    const int m0 = blockIdx.x * 128;
    const int n0 = blockIdx.y * 128;
    const int wm = (wid >> 1) * 32;   // warp m offset
    const int wn = (wid & 1) * 64;    // warp n offset

    // loader: thread t covers row t/2, 16B-chunks {2*(t&1), 2*(t&1)+1}
    const int lrow = tid >> 1;
    const int lch  = (tid & 1) * 2;
    const size_t gA = (size_t)(m0 + lrow) * DM;
    const size_t gB = (size_t)(n0 + lrow) * DM;

    auto load_stage = [&](int c, int s) {
        const uint32_t st = sbase + s * STAGE_BYTES;
        const int k0 = c * BK + lch * 8;
        const uint32_t so = lrow * (RS*2) + lch * 16;
        cpa16(st + so,                        Ahp + gA + k0);
        cpa16(st + so + 16,                   Ahp + gA + k0 + 8);
        cpa16(st + TILE_BYTES   + so,         Alp + gA + k0);
        cpa16(st + TILE_BYTES   + so + 16,    Alp + gA + k0 + 8);
        cpa16(st + 2*TILE_BYTES + so,         BhT + gB + k0);
        cpa16(st + 2*TILE_BYTES + so + 16,    BhT + gB + k0 + 8);
        cpa16(st + 3*TILE_BYTES + so,         BlT + gB + k0);
        cpa16(st + 3*TILE_BYTES + so + 16,    BlT + gB + k0 + 8);
        asm volatile("cp.async.commit_group;" ::: "memory");
    };

    float acc[2][8][4];
#pragma unroll
    for (int mt = 0; mt < 2; ++mt)
#pragma unroll
        for (int nt = 0; nt < 8; ++nt)
#pragma unroll
            for (int j = 0; j < 4; ++j) acc[mt][nt][j] = 0.f;

    load_stage(0, 0);
    load_stage(1, 1);

    // precomputed ldmatrix lane addressing
    const int a_row  = (lane & 15);
    const int a_colb = (lane & 16) ? 16 : 0;
    const int b_row  = ((lane & 16) ? 8 : 0) + (lane & 7);
    const int b_colb = (lane & 8) ? 16 : 0;

    for (int c = 0; c < NCHUNK; ++c) {
        if (c < NCHUNK - 1) asm volatile("cp.async.wait_group 1;" ::: "memory");
        else                asm volatile("cp.async.wait_group 0;" ::: "memory");
        __syncthreads();
        const uint32_t st = sbase + (c & 1) * STAGE_BYTES;
#pragma unroll
        for (int k16 = 0; k16 < 2; ++k16) {
            uint32_t ah[2][4], al[2][4], bh[16], bl[16];
#pragma unroll
            for (int mt = 0; mt < 2; ++mt) {
                const uint32_t a0 = st + (wm + mt*16 + a_row) * (RS*2)
                                       + k16*32 + a_colb;
                ldsm4(ah[mt], a0);
                ldsm4(al[mt], a0 + TILE_BYTES);
            }
#pragma unroll
            for (int p = 0; p < 4; ++p) {
                const uint32_t b0 = st + 2*TILE_BYTES
                                  + (wn + p*16 + b_row) * (RS*2)
                                  + k16*32 + b_colb;
                ldsm4(&bh[4*p], b0);
                ldsm4(&bl[4*p], b0 + TILE_BYTES);
            }
#pragma unroll
            for (int mt = 0; mt < 2; ++mt)
#pragma unroll
                for (int nt = 0; nt < 8; ++nt) {
                    mma16816(acc[mt][nt], ah[mt], &bh[nt*2]);
                    mma16816(acc[mt][nt], ah[mt], &bl[nt*2]);
                    mma16816(acc[mt][nt], al[mt], &bh[nt*2]);
                }
        }
        __syncthreads();
        if (c + 2 < NCHUNK) load_stage(c + 2, c & 1);
    }

    // Epilogue: c fragment rows l/4 (+8), cols (l&3)*2
    const int er = lane >> 2;
    const int ec = (lane & 3) * 2;
#pragma unroll
    for (int mt = 0; mt < 2; ++mt) {
        const int row = m0 + wm + mt*16 + er;
#pragma unroll
        for (int nt = 0; nt < 8; ++nt) {
            const int col = n0 + wn + nt*8 + ec;
            const float b0 = bias[col], b1 = bias[col + 1];
            float2 v0 = { acc[mt][nt][0] + b0, acc[mt][nt][1] + b1 };
            float2 v1 = { acc[mt][nt][2] + b0, acc[mt][nt][3] + b1 };
            *(float2*)(C + (size_t)row * DM + col)       = v0;
            *(float2*)(C + (size_t)(row + 8) * DM + col) = v1;
        }
    }
}

// ---------------------------------------------------------------------------
// Flash attention (fp32) — unchanged (known-good).
// ---------------------------------------------------------------------------
__global__ __launch_bounds__(256) void attn_kernel(
    const float* __restrict__ Qp, const float* __restrict__ Kp,
    const float* __restrict__ Vp, float* __restrict__ Ao)
{
    __shared__ float QsT[64*64];
    __shared__ float KPs[64*64];
    __shared__ float Vs [64*64];

    const int tid = threadIdx.x;
    const int tx  = tid & 15;
    const int ty  = tid >> 4;
    const int qblk = blockIdx.x;
    const int hb   = blockIdx.y;
    const int b    = hb & 1;
    const int h    = hb >> 1;
    const int base = b*SL*DM + h*64;
    const int q0   = qblk * 64;

    const int l_dg  = tid & 15;
    const int l_row = tid >> 4;

#pragma unroll
    for (int r = 0; r < 4; ++r) {
        const int m = l_row + r*16;
        const int d = l_dg * 4;
        float4 v4 = *(const float4*)(Qp + base + (q0+m)*DM + d);
        v4.x *= 0.125f; v4.y *= 0.125f; v4.z *= 0.125f; v4.w *= 0.125f;
        QsT[(d+0)*64 + 4*((m>>2) ^ ((d+0)&15)) + (m&3)] = v4.x;
        QsT[(d+1)*64 + 4*((m>>2) ^ ((d+1)&15)) + (m&3)] = v4.y;
        QsT[(d+2)*64 + 4*((m>>2) ^ ((d+2)&15)) + (m&3)] = v4.z;
        QsT[(d+3)*64 + 4*((m>>2) ^ ((d+3)&15)) + (m&3)] = v4.w;
    }

    float acc[4][4];
#pragma unroll
    for (int i = 0; i < 4; ++i)
#pragma unroll
        for (int j = 0; j < 4; ++j) acc[i][j] = 0.f;
    float mrow[4] = {-INFINITY, -INFINITY, -INFINITY, -INFINITY};
    float lrow[4] = {0.f, 0.f, 0.f, 0.f};

    for (int it = 0; it < SL/64; ++it) {
        const int k0 = it * 64;
        __syncthreads();
#pragma unroll
        for (int r = 0; r < 4; ++r) {
            const int n = l_row + r*16;
            const int d = l_dg * 4;
            float4 kv = *(const float4*)(Kp + base + (k0+n)*DM + d);
            float4 vv = *(const float4*)(Vp + base + (k0+n)*DM + d);
            KPs[(d+0)*64 + 4*((n>>2) ^ ((d+0)&15)) + (n&3)] = kv.x;
            KPs[(d+1)*64 + 4*((n>>2) ^ ((d+1)&15)) + (n&3)] = kv.y;
            KPs[(d+2)*64 + 4*((n>>2) ^ ((d+2)&15)) + (n&3)] = kv.z;
            KPs[(d+3)*64 + 4*((n>>2) ^ ((d+3)&15)) + (n&3)] = kv.w;
            *(float4*)(Vs + n*64 + d) = vv;
        }
        __syncthreads();

        float s[4][4];
#pragma unroll
        for (int i = 0; i < 4; ++i)
#pragma unroll
            for (int j = 0; j < 4; ++j) s[i][j] = 0.f;
#pragma unroll 8
        for (int d = 0; d < 64; ++d) {
            const float4 qv = *(const float4*)(QsT + d*64 + 4*(ty ^ (d & 15)));
            const float4 kv = *(const float4*)(KPs + d*64 + 4*(tx ^ (d & 15)));
            const float qa[4] = {qv.x, qv.y, qv.z, qv.w};
            const float ka[4] = {kv.x, kv.y, kv.z, kv.w};
#pragma unroll
            for (int i = 0; i < 4; ++i)
#pragma unroll
                for (int j = 0; j < 4; ++j)
                    s[i][j] += qa[i] * ka[j];
        }

        float mx[4];
#pragma unroll
        for (int i = 0; i < 4; ++i)
            mx[i] = fmaxf(fmaxf(s[i][0], s[i][1]), fmaxf(s[i][2], s[i][3]));
#pragma unroll
        for (int off = 8; off >= 1; off >>= 1)
#pragma unroll
            for (int i = 0; i < 4; ++i)
                mx[i] = fmaxf(mx[i], __shfl_xor_sync(0xffffffffu, mx[i], off));

        float corr[4], rs[4];
#pragma unroll
        for (int i = 0; i < 4; ++i) {
            const float mnew = fmaxf(mrow[i], mx[i]);
            corr[i] = __expf(mrow[i] - mnew);
            mrow[i] = mnew;
            float r = 0.f;
#pragma unroll
            for (int j = 0; j < 4; ++j) {
                s[i][j] = __expf(s[i][j] - mnew);
                r += s[i][j];
            }
            rs[i] = r;
        }
#pragma unroll
        for (int off = 8; off >= 1; off >>= 1)
#pragma unroll
            for (int i = 0; i < 4; ++i)
                rs[i] += __shfl_xor_sync(0xffffffffu, rs[i], off);
#pragma unroll
        for (int i = 0; i < 4; ++i) {
            lrow[i] = lrow[i] * corr[i] + rs[i];
#pragma unroll
            for (int j = 0; j < 4; ++j) acc[i][j] *= corr[i];
        }

        __syncthreads();
#pragma unroll
        for (int j = 0; j < 4; ++j) {
            const int n = 4*tx + j;
            float* dst = KPs + n*64 + 4*(ty ^ (n & 15));
#pragma unroll
            for (int i = 0; i < 4; ++i) dst[i] = s[i][j];
        }
        __syncthreads();

#pragma unroll 8
        for (int kk = 0; kk < 64; ++kk) {
            const float4 pv = *(const float4*)(KPs + kk*64 + 4*(ty ^ (kk & 15)));
            const float4 vv = *(const float4*)(Vs  + kk*64 + 4*tx);
            const float pa[4] = {pv.x, pv.y, pv.z, pv.w};
            const float va[4] = {vv.x, vv.y, vv.z, vv.w};
#pragma unroll
            for (int i = 0; i < 4; ++i)
#pragma unroll
                for (int j = 0; j < 4; ++j)
                    acc[i][j] += pa[i] * va[j];
        }
    }

#pragma unroll
    for (int i = 0; i < 4; ++i) {
        const float inv = 1.f / lrow[i];
        float4 o;
        o.x = acc[i][0]*inv; o.y = acc[i][1]*inv;
        o.z = acc[i][2]*inv; o.w = acc[i][3]*inv;
        *(float4*)(Ao + base + (q0 + 4*ty + i)*DM + 4*tx) = o;
    }
}

// ---------------------------------------------------------------------------
extern "C" void kernel_launch(void* const* d_in, const int* in_sizes, int n_in,
                              void* d_out, int out_size)
{
    const float* q   = (const float*)d_in[0];
    const float* k   = (const float*)d_in[1];
    const float* v   = (const float*)d_in[2];
    const float* w_q = (const float*)d_in[3];
    const float* b_q = (const float*)d_in[4];
    const float* w_k = (const float*)d_in[5];
    const float* b_k = (const float*)d_in[6];
    const float* w_v = (const float*)d_in[7];
    const float* b_v = (const float*)d_in[8];
    const float* w_o = (const float*)d_in[9];
    const float* b_o = (const float*)d_in[10];
    float* out = (float*)d_out;

    cudaFuncSetAttribute(gemm_mma_kernel,
                         cudaFuncAttributeMaxDynamicSharedMemorySize, GEMM_SMEM);

    float *gq, *gk, *gv, *gao;
    cudaGetSymbolAddress((void**)&gq,  g_q);
    cudaGetSymbolAddress((void**)&gk,  g_k);
    cudaGetSymbolAddress((void**)&gv,  g_v);
    cudaGetSymbolAddress((void**)&gao, g_ao);
    __nv_bfloat16 *qh,*ql,*kh,*kl,*vh,*vl,*aoh,*aol;
    __nv_bfloat16 *wqh,*wql,*wkh,*wkl,*wvh,*wvl,*woh,*wol;
    cudaGetSymbolAddress((void**)&qh,  g_qh);  cudaGetSymbolAddress((void**)&ql,  g_ql);
    cudaGetSymbolAddress((void**)&kh,  g_kh);  cudaGetSymbolAddress((void**)&kl,  g_kl);
    cudaGetSymbolAddress((void**)&vh,  g_vh);  cudaGetSymbolAddress((void**)&vl,  g_vl);
    cudaGetSymbolAddress((void**)&aoh, g_aoh); cudaGetSymbolAddress((void**)&aol, g_aol);
    cudaGetSymbolAddress((void**)&wqh, g_wqh); cudaGetSymbolAddress((void**)&wql, g_wql);
    cudaGetSymbolAddress((void**)&wkh, g_wkh); cudaGetSymbolAddress((void**)&wkl, g_wkl);
    cudaGetSymbolAddress((void**)&wvh, g_wvh); cudaGetSymbolAddress((void**)&wvl, g_wvl);
    cudaGetSymbolAddress((void**)&woh, g_woh); cudaGetSymbolAddress((void**)&wol, g_wol);

    const int n2 = MR * DM / 2;
    const dim3 sgrid((n2 + 255) / 256), sblk(256);
    split2_kernel<<<sgrid, sblk>>>(q, (__nv_bfloat162*)qh, (__nv_bfloat162*)ql, n2);
    split2_kernel<<<sgrid, sblk>>>(k, (__nv_bfloat162*)kh, (__nv_bfloat162*)kl, n2);
    split2_kernel<<<sgrid, sblk>>>(v, (__nv_bfloat162*)vh, (__nv_bfloat162*)vl, n2);

    const dim3 tgrid(DM/32, DM/32), tblk(32, 8);
    tsplit_kernel<<<tgrid, tblk>>>(w_q, wqh, wql);
    tsplit_kernel<<<tgrid, tblk>>>(w_k, wkh, wkl);
    tsplit_kernel<<<tgrid, tblk>>>(w_v, wvh, wvl);
    tsplit_kernel<<<tgrid, tblk>>>(w_o, woh, wol);

    const dim3 ggrid(MR/128, DM/128);    // (32, 8)
    gemm_mma_kernel<<<ggrid, 256, GEMM_SMEM>>>(qh, ql, wqh, wql, b_q, gq);
    gemm_mma_kernel<<<ggrid, 256, GEMM_SMEM>>>(kh, kl, wkh, wkl, b_k, gk);
    gemm_mma_kernel<<<ggrid, 256, GEMM_SMEM>>>(vh, vl, wvh, wvl, b_v, gv);

    attn_kernel<<<dim3(SL/64, NH*BSZ), 256>>>(gq, gk, gv, gao);

    split2_kernel<<<sgrid, sblk>>>(gao, (__nv_bfloat162*)aoh, (__nv_bfloat162*)aol, n2);
    gemm_mma_kernel<<<ggrid, 256, GEMM_SMEM>>>(aoh, aol, woh, wol, b_o, out);
}

// round 4
// speedup vs baseline: 2.4312x; 1.9128x over previous
#include <cuda_runtime.h>
#include <cuda_bf16.h>
#include <math.h>
#include <stdint.h>

#define DM 1024
#define BSZ 2
#define SL  2048
#define NH  16
#define MR  (BSZ*SL)   // 4096 rows for projection GEMMs

// ---------------------------------------------------------------------------
// Scratch (device globals: allocation-free per harness rules)
// ---------------------------------------------------------------------------
__device__ float g_q [MR*DM];
__device__ float g_k [MR*DM];
__device__ float g_v [MR*DM];
__device__ float g_ao[MR*DM];

__device__ __nv_bfloat16 g_qh[MR*DM], g_ql[MR*DM];
__device__ __nv_bfloat16 g_kh[MR*DM], g_kl[MR*DM];
__device__ __nv_bfloat16 g_vh[MR*DM], g_vl[MR*DM];
__device__ __nv_bfloat16 g_aoh[MR*DM], g_aol[MR*DM];
__device__ __nv_bfloat16 g_wqh[DM*DM], g_wql[DM*DM];
__device__ __nv_bfloat16 g_wkh[DM*DM], g_wkl[DM*DM];
__device__ __nv_bfloat16 g_wvh[DM*DM], g_wvl[DM*DM];
__device__ __nv_bfloat16 g_woh[DM*DM], g_wol[DM*DM];

// ---------------------------------------------------------------------------
// Helpers (family-portable PTX only: cp.async, ldmatrix, mma.sync)
// ---------------------------------------------------------------------------
__device__ __forceinline__ uint32_t smem_u32(const void* p) {
    uint32_t a;
    asm("{ .reg .u64 t; cvta.to.shared.u64 t, %1; cvt.u32.u64 %0, t; }"
        : "=r"(a) : "l"(p));
    return a;
}
__device__ __forceinline__ void cpa16(uint32_t dst, const void* src) {
    asm volatile("cp.async.cg.shared.global [%0], [%1], 16;" :: "r"(dst), "l"(src));
}
__device__ __forceinline__ void ldsm4(uint32_t* r, uint32_t addr) {
    asm volatile("ldmatrix.sync.aligned.m8n8.x4.shared.b16 {%0,%1,%2,%3}, [%4];"
        : "=r"(r[0]), "=r"(r[1]), "=r"(r[2]), "=r"(r[3]) : "r"(addr));
}
__device__ __forceinline__ void mma16816(float* c, const uint32_t* a, const uint32_t* b) {
    asm volatile("mma.sync.aligned.m16n8k16.row.col.f32.bf16.bf16.f32 "
        "{%0,%1,%2,%3}, {%4,%5,%6,%7}, {%8,%9}, {%0,%1,%2,%3};"
        : "+f"(c[0]), "+f"(c[1]), "+f"(c[2]), "+f"(c[3])
        : "r"(a[0]), "r"(a[1]), "r"(a[2]), "r"(a[3]), "r"(b[0]), "r"(b[1]));
}
__device__ __forceinline__ void mma_tf32(float* c, const uint32_t* a, const uint32_t* b) {
    asm volatile("mma.sync.aligned.m16n8k8.row.col.f32.tf32.tf32.f32 "
        "{%0,%1,%2,%3}, {%4,%5,%6,%7}, {%8,%9}, {%0,%1,%2,%3};"
        : "+f"(c[0]), "+f"(c[1]), "+f"(c[2]), "+f"(c[3])
        : "r"(a[0]), "r"(a[1]), "r"(a[2]), "r"(a[3]), "r"(b[0]), "r"(b[1]));
}
__device__ __forceinline__ float tf32_rna(float x) {
    uint32_t u;
    asm("cvt.rna.tf32.f32 %0, %1;" : "=r"(u) : "f"(x));
    return __uint_as_float(u);
}

// ---------------------------------------------------------------------------
// Split conversion kernels (fp32 -> hi/lo bf16)
// ---------------------------------------------------------------------------
__global__ void split2_kernel(const float* __restrict__ x,
                              __nv_bfloat162* __restrict__ h,
                              __nv_bfloat162* __restrict__ l, int n2)
{
    int i = blockIdx.x * blockDim.x + threadIdx.x;
    if (i < n2) {
        float2 v = ((const float2*)x)[i];
        __nv_bfloat16 h0 = __float2bfloat16(v.x);
        __nv_bfloat16 h1 = __float2bfloat16(v.y);
        __nv_bfloat16 l0 = __float2bfloat16(v.x - __bfloat162float(h0));
        __nv_bfloat16 l1 = __float2bfloat16(v.y - __bfloat162float(h1));
        h[i] = __halves2bfloat162(h0, h1);
        l[i] = __halves2bfloat162(l0, l1);
    }
}

// Transpose + split: W[k][n] (1024x1024 fp32) -> hT/lT[n][k] bf16
__global__ void tsplit_kernel(const float* __restrict__ W,
                              __nv_bfloat16* __restrict__ hT,
                              __nv_bfloat16* __restrict__ lT)
{
    __shared__ float t[32][33];
    const int tx = threadIdx.x, ty = threadIdx.y;   // 32 x 8
    const int n0 = blockIdx.x * 32, k0 = blockIdx.y * 32;
#pragma unroll
    for (int r = 0; r < 4; ++r)
        t[ty + 8*r][tx] = W[(k0 + ty + 8*r) * DM + n0 + tx];
    __syncthreads();
#pragma unroll
    for (int r = 0; r < 4; ++r) {
        const int n = n0 + ty + 8*r;
        const float v = t[tx][ty + 8*r];
        __nv_bfloat16 h = __float2bfloat16(v);
        __nv_bfloat16 l = __float2bfloat16(v - __bfloat162float(h));
        hT[n * DM + k0 + tx] = h;
        lT[n * DM + k0 + tx] = l;
    }
}

// ---------------------------------------------------------------------------
// mma.sync bf16x3 GEMM (unchanged from R2, plus optional tf32 output rounding)
// ---------------------------------------------------------------------------
#define BK 32
#define RS 40
#define TILE_BYTES (128*RS*2)
#define STAGE_BYTES (4*TILE_BYTES)
#define GEMM_SMEM (2*STAGE_BYTES)
#define NCHUNK (DM/BK)

__global__ __launch_bounds__(256) void gemm_mma_kernel(
    const __nv_bfloat16* __restrict__ Ahp, const __nv_bfloat16* __restrict__ Alp,
    const __nv_bfloat16* __restrict__ BhT, const __nv_bfloat16* __restrict__ BlT,
    const float* __restrict__ bias, float* __restrict__ C, int rnd_tf32)
{
    extern __shared__ char smem[];
    const uint32_t sbase = smem_u32(smem);
    const int tid  = threadIdx.x;
    const int wid  = tid >> 5;
    const int lane = tid & 31;
    const int m0 = blockIdx.x * 128;
    const int n0 = blockIdx.y * 128;
    const int wm = (wid >> 1) * 32;
    const int wn = (wid & 1) * 64;

    const int lrow = tid >> 1;
    const int lch  = (tid & 1) * 2;
    const size_t gA = (size_t)(m0 + lrow) * DM;
    const size_t gB = (size_t)(n0 + lrow) * DM;

    auto load_stage = [&](int c, int s) {
        const uint32_t st = sbase + s * STAGE_BYTES;
        const int k0 = c * BK + lch * 8;
        const uint32_t so = lrow * (RS*2) + lch * 16;
        cpa16(st + so,                        Ahp + gA + k0);
        cpa16(st + so + 16,                   Ahp + gA + k0 + 8);
        cpa16(st + TILE_BYTES   + so,         Alp + gA + k0);
        cpa16(st + TILE_BYTES   + so + 16,    Alp + gA + k0 + 8);
        cpa16(st + 2*TILE_BYTES + so,         BhT + gB + k0);
        cpa16(st + 2*TILE_BYTES + so + 16,    BhT + gB + k0 + 8);
        cpa16(st + 3*TILE_BYTES + so,         BlT + gB + k0);
        cpa16(st + 3*TILE_BYTES + so + 16,    BlT + gB + k0 + 8);
        asm volatile("cp.async.commit_group;" ::: "memory");
    };

    float acc[2][8][4];
#pragma unroll
    for (int mt = 0; mt < 2; ++mt)
#pragma unroll
        for (int nt = 0; nt < 8; ++nt)
#pragma unroll
            for (int j = 0; j < 4; ++j) acc[mt][nt][j] = 0.f;

    load_stage(0, 0);
    load_stage(1, 1);

    const int a_row  = (lane & 15);
    const int a_colb = (lane & 16) ? 16 : 0;
    const int b_row  = ((lane & 16) ? 8 : 0) + (lane & 7);
    const int b_colb = (lane & 8) ? 16 : 0;

    for (int c = 0; c < NCHUNK; ++c) {
        if (c < NCHUNK - 1) asm volatile("cp.async.wait_group 1;" ::: "memory");
        else                asm volatile("cp.async.wait_group 0;" ::: "memory");
        __syncthreads();
        const uint32_t st = sbase + (c & 1) * STAGE_BYTES;
#pragma unroll
        for (int k16 = 0; k16 < 2; ++k16) {
            uint32_t ah[2][4], al[2][4], bh[16], bl[16];
#pragma unroll
            for (int mt = 0; mt < 2; ++mt) {
                const uint32_t a0 = st + (wm + mt*16 + a_row) * (RS*2)
                                       + k16*32 + a_colb;
                ldsm4(ah[mt], a0);
                ldsm4(al[mt], a0 + TILE_BYTES);
            }
#pragma unroll
            for (int p = 0; p < 4; ++p) {
                const uint32_t b0 = st + 2*TILE_BYTES
                                  + (wn + p*16 + b_row) * (RS*2)
                                  + k16*32 + b_colb;
                ldsm4(&bh[4*p], b0);
                ldsm4(&bl[4*p], b0 + TILE_BYTES);
            }
#pragma unroll
            for (int mt = 0; mt < 2; ++mt)
#pragma unroll
                for (int nt = 0; nt < 8; ++nt) {
                    mma16816(acc[mt][nt], ah[mt], &bh[nt*2]);
                    mma16816(acc[mt][nt], ah[mt], &bl[nt*2]);
                    mma16816(acc[mt][nt], al[mt], &bh[nt*2]);
                }
        }
        __syncthreads();
        if (c + 2 < NCHUNK) load_stage(c + 2, c & 1);
    }

    const int er = lane >> 2;
    const int ec = (lane & 3) * 2;
#pragma unroll
    for (int mt = 0; mt < 2; ++mt) {
        const int row = m0 + wm + mt*16 + er;
#pragma unroll
        for (int nt = 0; nt < 8; ++nt) {
            const int col = n0 + wn + nt*8 + ec;
            const float b0 = bias[col], b1 = bias[col + 1];
            float2 v0 = { acc[mt][nt][0] + b0, acc[mt][nt][1] + b1 };
            float2 v1 = { acc[mt][nt][2] + b0, acc[mt][nt][3] + b1 };
            if (rnd_tf32) {
                v0.x = tf32_rna(v0.x); v0.y = tf32_rna(v0.y);
                v1.x = tf32_rna(v1.x); v1.y = tf32_rna(v1.y);
            }
            *(float2*)(C + (size_t)row * DM + col)       = v0;
            *(float2*)(C + (size_t)(row + 8) * DM + col) = v1;
        }
    }
}

// ---------------------------------------------------------------------------
// tf32 mma.sync flash attention.
//   grid = (SL/128, NH*BSZ), 256 threads = 8 warps; warp w owns q-rows 16w..+15.
//   KV tiles of 64 keys, cp.async double-buffered, smem stride 68 words.
//   Inputs (g_q/g_k/g_v) are pre-rounded to tf32 by the projection epilogue.
// ---------------------------------------------------------------------------
#define SP 68
#define KV_FLOATS (64*SP)                       // one KV tile
#define ATT_SMEM ((4*KV_FLOATS + 128*SP) * 4)   // Ks[2] + Vs[2] + Ps = 104448 B
#define NIT (SL/64)                             // 32

__global__ __launch_bounds__(256) void attn_mma_kernel(
    const float* __restrict__ Qp, const float* __restrict__ Kp,
    const float* __restrict__ Vp, float* __restrict__ Ao)
{
    extern __shared__ float fsm[];
    float* KsB = fsm;                    // [2][64][SP]
    float* VsB = fsm + 2*KV_FLOATS;      // [2][64][SP]
    float* Ps  = fsm + 4*KV_FLOATS;      // [128][SP] (per-warp 16-row slabs)
    const uint32_t sb = smem_u32(fsm);

    const int tid = threadIdx.x, wid = tid >> 5, lane = tid & 31;
    const int g = lane >> 2, tg = lane & 3;
    const int hb = blockIdx.y;
    const size_t base = (size_t)(hb & 1) * SL * DM + (size_t)(hb >> 1) * 64;
    const int q0 = blockIdx.x * 128;

    // ---- Q A-fragments (rows 16w+g, 16w+g+8; loop-invariant), pre-scaled ----
    uint32_t aq[8][4];
    {
        const float* Qr0 = Qp + base + (size_t)(q0 + wid*16 + g) * DM;
        const float* Qr1 = Qr0 + (size_t)8 * DM;
#pragma unroll
        for (int kk = 0; kk < 8; ++kk) {
            aq[kk][0] = __float_as_uint(Qr0[kk*8 + tg]     * 0.125f);
            aq[kk][1] = __float_as_uint(Qr1[kk*8 + tg]     * 0.125f);
            aq[kk][2] = __float_as_uint(Qr0[kk*8 + tg + 4] * 0.125f);
            aq[kk][3] = __float_as_uint(Qr1[kk*8 + tg + 4] * 0.125f);
        }
    }

    // ---- KV loader: thread t -> row t/4, four 16B chunks ----
    const int l_row = tid >> 2;
    const int l_c0  = (tid & 3) * 16;    // float col base (4 chunks of 4 floats)
    auto loadKV = [&](int it, int s) {
        const float* Kg = Kp + base + (size_t)(it*64 + l_row) * DM + l_c0;
        const float* Vg = Vp + base + (size_t)(it*64 + l_row) * DM + l_c0;
        const uint32_t kd = sb + ((s*64 + l_row) * SP + l_c0) * 4;
        const uint32_t vd = kd + 2*KV_FLOATS*4;
#pragma unroll
        for (int cc = 0; cc < 4; ++cc) {
            cpa16(kd + cc*16, Kg + cc*4);
            cpa16(vd + cc*16, Vg + cc*4);
        }
        asm volatile("cp.async.commit_group;" ::: "memory");
    };

    float acc[8][4];
#pragma unroll
    for (int j = 0; j < 8; ++j)
#pragma unroll
        for (int i = 0; i < 4; ++i) acc[j][i] = 0.f;
    float m0 = -INFINITY, m1 = -INFINITY, l0 = 0.f, l1 = 0.f;

    float* Pw = Ps + wid * 16 * SP;

    loadKV(0, 0);
    loadKV(1, 1);

    for (int it = 0; it < NIT; ++it) {
        const int s = it & 1;
        if (it < NIT - 1) asm volatile("cp.async.wait_group 1;" ::: "memory");
        else              asm volatile("cp.async.wait_group 0;" ::: "memory");
        __syncthreads();
        const float* Kt = KsB + s * KV_FLOATS;
        const float* Vt = VsB + s * KV_FLOATS;

        // ---- S = Q @ K^T (64 cols) ----
        float sc[8][4];
#pragma unroll
        for (int j = 0; j < 8; ++j)
#pragma unroll
            for (int i = 0; i < 4; ++i) sc[j][i] = 0.f;
#pragma unroll
        for (int kk = 0; kk < 8; ++kk) {
            uint32_t bv[8][2];
#pragma unroll
            for (int j = 0; j < 8; ++j) {
                bv[j][0] = __float_as_uint(Kt[(8*j + g) * SP + kk*8 + tg]);
                bv[j][1] = __float_as_uint(Kt[(8*j + g) * SP + kk*8 + tg + 4]);
            }
#pragma unroll
            for (int j = 0; j < 8; ++j) mma_tf32(sc[j], aq[kk], bv[j]);
        }

        // ---- online softmax (2 rows per lane; reduce over tg via xor 1,2) ---
        float mx0 = -INFINITY, mx1 = -INFINITY;
#pragma unroll
        for (int j = 0; j < 8; ++j) {
            mx0 = fmaxf(mx0, fmaxf(sc[j][0], sc[j][1]));
            mx1 = fmaxf(mx1, fmaxf(sc[j][2], sc[j][3]));
        }
        mx0 = fmaxf(mx0, __shfl_xor_sync(0xffffffffu, mx0, 1));
        mx0 = fmaxf(mx0, __shfl_xor_sync(0xffffffffu, mx0, 2));
        mx1 = fmaxf(mx1, __shfl_xor_sync(0xffffffffu, mx1, 1));
        mx1 = fmaxf(mx1, __shfl_xor_sync(0xffffffffu, mx1, 2));

        const float mn0 = fmaxf(m0, mx0), mn1 = fmaxf(m1, mx1);
        const float c0 = __expf(m0 - mn0), c1 = __expf(m1 - mn1);
        m0 = mn0; m1 = mn1;
        float rs0 = 0.f, rs1 = 0.f;
#pragma unroll
        for (int j = 0; j < 8; ++j) {
            sc[j][0] = __expf(sc[j][0] - mn0);
            sc[j][1] = __expf(sc[j][1] - mn0);
            sc[j][2] = __expf(sc[j][2] - mn1);
            sc[j][3] = __expf(sc[j][3] - mn1);
            rs0 += sc[j][0] + sc[j][1];
            rs1 += sc[j][2] + sc[j][3];
        }
        rs0 += __shfl_xor_sync(0xffffffffu, rs0, 1);
        rs0 += __shfl_xor_sync(0xffffffffu, rs0, 2);
        rs1 += __shfl_xor_sync(0xffffffffu, rs1, 1);
        rs1 += __shfl_xor_sync(0xffffffffu, rs1, 2);
        l0 = l0 * c0 + rs0;
        l1 = l1 * c1 + rs1;
#pragma unroll
        for (int j = 0; j < 8; ++j) {
            acc[j][0] *= c0; acc[j][1] *= c0;
            acc[j][2] *= c1; acc[j][3] *= c1;
        }

        // ---- P -> warp-local smem slab (tf32-rounded) ----
#pragma unroll
        for (int j = 0; j < 8; ++j) {
            float2 plo = { tf32_rna(sc[j][0]), tf32_rna(sc[j][1]) };
            float2 phi = { tf32_rna(sc[j][2]), tf32_rna(sc[j][3]) };
            *(float2*)(Pw + g * SP       + 8*j + 2*tg) = plo;
            *(float2*)(Pw + (g + 8) * SP + 8*j + 2*tg) = phi;
        }
        __syncwarp();

        // ---- O += P @ V ----
#pragma unroll
        for (int kk = 0; kk < 8; ++kk) {
            uint32_t ap[4];
            ap[0] = __float_as_uint(Pw[g * SP       + kk*8 + tg]);
            ap[1] = __float_as_uint(Pw[(g + 8) * SP + kk*8 + tg]);
            ap[2] = __float_as_uint(Pw[g * SP       + kk*8 + tg + 4]);
            ap[3] = __float_as_uint(Pw[(g + 8) * SP + kk*8 + tg + 4]);
            uint32_t bv[8][2];
#pragma unroll
            for (int j = 0; j < 8; ++j) {
                bv[j][0] = __float_as_uint(Vt[(kk*8 + tg)     * SP + 8*j + g]);
                bv[j][1] = __float_as_uint(Vt[(kk*8 + tg + 4) * SP + 8*j + g]);
            }
#pragma unroll
            for (int j = 0; j < 8; ++j) mma_tf32(acc[j], ap, bv[j]);
        }

        __syncthreads();
        if (it + 2 < NIT) loadKV(it + 2, s);
    }

    // ---- epilogue: normalize and store ----
    const float i0 = 1.f / l0, i1 = 1.f / l1;
    float* Or0 = Ao + base + (size_t)(q0 + wid*16 + g) * DM;
    float* Or1 = Or0 + (size_t)8 * DM;
#pragma unroll
    for (int j = 0; j < 8; ++j) {
        float2 v0 = { acc[j][0] * i0, acc[j][1] * i0 };
        float2 v1 = { acc[j][2] * i1, acc[j][3] * i1 };
        *(float2*)(Or0 + 8*j + 2*tg) = v0;
        *(float2*)(Or1 + 8*j + 2*tg) = v1;
    }
}

// ---------------------------------------------------------------------------
extern "C" void kernel_launch(void* const* d_in, const int* in_sizes, int n_in,
                              void* d_out, int out_size)
{
    const float* q   = (const float*)d_in[0];
    const float* k   = (const float*)d_in[1];
    const float* v   = (const float*)d_in[2];
    const float* w_q = (const float*)d_in[3];
    const float* b_q = (const float*)d_in[4];
    const float* w_k = (const float*)d_in[5];
    const float* b_k = (const float*)d_in[6];
    const float* w_v = (const float*)d_in[7];
    const float* b_v = (const float*)d_in[8];
    const float* w_o = (const float*)d_in[9];
    const float* b_o = (const float*)d_in[10];
    float* out = (float*)d_out;

    cudaFuncSetAttribute(gemm_mma_kernel,
                         cudaFuncAttributeMaxDynamicSharedMemorySize, GEMM_SMEM);
    cudaFuncSetAttribute(attn_mma_kernel,
                         cudaFuncAttributeMaxDynamicSharedMemorySize, ATT_SMEM);

    float *gq, *gk, *gv, *gao;
    cudaGetSymbolAddress((void**)&gq,  g_q);
    cudaGetSymbolAddress((void**)&gk,  g_k);
    cudaGetSymbolAddress((void**)&gv,  g_v);
    cudaGetSymbolAddress((void**)&gao, g_ao);
    __nv_bfloat16 *qh,*ql,*kh,*kl,*vh,*vl,*aoh,*aol;
    __nv_bfloat16 *wqh,*wql,*wkh,*wkl,*wvh,*wvl,*woh,*wol;
    cudaGetSymbolAddress((void**)&qh,  g_qh);  cudaGetSymbolAddress((void**)&ql,  g_ql);
    cudaGetSymbolAddress((void**)&kh,  g_kh);  cudaGetSymbolAddress((void**)&kl,  g_kl);
    cudaGetSymbolAddress((void**)&vh,  g_vh);  cudaGetSymbolAddress((void**)&vl,  g_vl);
    cudaGetSymbolAddress((void**)&aoh, g_aoh); cudaGetSymbolAddress((void**)&aol, g_aol);
    cudaGetSymbolAddress((void**)&wqh, g_wqh); cudaGetSymbolAddress((void**)&wql, g_wql);
    cudaGetSymbolAddress((void**)&wkh, g_wkh); cudaGetSymbolAddress((void**)&wkl, g_wkl);
    cudaGetSymbolAddress((void**)&wvh, g_wvh); cudaGetSymbolAddress((void**)&wvl, g_wvl);
    cudaGetSymbolAddress((void**)&woh, g_woh); cudaGetSymbolAddress((void**)&wol, g_wol);

    const int n2 = MR * DM / 2;
    const dim3 sgrid((n2 + 255) / 256), sblk(256);
    split2_kernel<<<sgrid, sblk>>>(q, (__nv_bfloat162*)qh, (__nv_bfloat162*)ql, n2);
    split2_kernel<<<sgrid, sblk>>>(k, (__nv_bfloat162*)kh, (__nv_bfloat162*)kl, n2);
    split2_kernel<<<sgrid, sblk>>>(v, (__nv_bfloat162*)vh, (__nv_bfloat162*)vl, n2);

    const dim3 tgrid(DM/32, DM/32), tblk(32, 8);
    tsplit_kernel<<<tgrid, tblk>>>(w_q, wqh, wql);
    tsplit_kernel<<<tgrid, tblk>>>(w_k, wkh, wkl);
    tsplit_kernel<<<tgrid, tblk>>>(w_v, wvh, wvl);
    tsplit_kernel<<<tgrid, tblk>>>(w_o, woh, wol);

    const dim3 ggrid(MR/128, DM/128);    // (32, 8)
    gemm_mma_kernel<<<ggrid, 256, GEMM_SMEM>>>(qh, ql, wqh, wql, b_q, gq, 1);
    gemm_mma_kernel<<<ggrid, 256, GEMM_SMEM>>>(kh, kl, wkh, wkl, b_k, gk, 1);
    gemm_mma_kernel<<<ggrid, 256, GEMM_SMEM>>>(vh, vl, wvh, wvl, b_v, gv, 1);

    attn_mma_kernel<<<dim3(SL/128, NH*BSZ), 256, ATT_SMEM>>>(gq, gk, gv, gao);

    split2_kernel<<<sgrid, sblk>>>(gao, (__nv_bfloat162*)aoh, (__nv_bfloat162*)aol, n2);
    gemm_mma_kernel<<<ggrid, 256, GEMM_SMEM>>>(aoh, aol, woh, wol, b_o, out, 0);
}

// round 7
// speedup vs baseline: 2.7234x; 1.1202x over previous
#include <cuda_runtime.h>
#include <cuda_bf16.h>
#include <math.h>
#include <stdint.h>

#define DM 1024
#define BSZ 2
#define SL  2048
#define NH  16
#define MR  (BSZ*SL)   // 4096 rows for projection GEMMs

// ---------------------------------------------------------------------------
// Scratch (device globals: allocation-free per harness rules)
// ---------------------------------------------------------------------------
__device__ float g_q [MR*DM];
__device__ float g_k [MR*DM];
__device__ float g_v [MR*DM];

__device__ __nv_bfloat16 g_qh[MR*DM], g_ql[MR*DM];
__device__ __nv_bfloat16 g_kh[MR*DM], g_kl[MR*DM];
__device__ __nv_bfloat16 g_vh[MR*DM], g_vl[MR*DM];
__device__ __nv_bfloat16 g_aoh[MR*DM], g_aol[MR*DM];
__device__ __nv_bfloat16 g_wqh[DM*DM], g_wql[DM*DM];
__device__ __nv_bfloat16 g_wkh[DM*DM], g_wkl[DM*DM];
__device__ __nv_bfloat16 g_wvh[DM*DM], g_wvl[DM*DM];
__device__ __nv_bfloat16 g_woh[DM*DM], g_wol[DM*DM];

// ---------------------------------------------------------------------------
// Helpers (family-portable PTX only: cp.async, ldmatrix, mma.sync)
// ---------------------------------------------------------------------------
__device__ __forceinline__ uint32_t smem_u32(const void* p) {
    uint32_t a;
    asm("{ .reg .u64 t; cvta.to.shared.u64 t, %1; cvt.u32.u64 %0, t; }"
        : "=r"(a) : "l"(p));
    return a;
}
__device__ __forceinline__ void cpa16(uint32_t dst, const void* src) {
    asm volatile("cp.async.cg.shared.global [%0], [%1], 16;" :: "r"(dst), "l"(src));
}
__device__ __forceinline__ void ldsm4(uint32_t* r, uint32_t addr) {
    asm volatile("ldmatrix.sync.aligned.m8n8.x4.shared.b16 {%0,%1,%2,%3}, [%4];"
        : "=r"(r[0]), "=r"(r[1]), "=r"(r[2]), "=r"(r[3]) : "r"(addr));
}
__device__ __forceinline__ void mma16816(float* c, const uint32_t* a, const uint32_t* b) {
    asm volatile("mma.sync.aligned.m16n8k16.row.col.f32.bf16.bf16.f32 "
        "{%0,%1,%2,%3}, {%4,%5,%6,%7}, {%8,%9}, {%0,%1,%2,%3};"
        : "+f"(c[0]), "+f"(c[1]), "+f"(c[2]), "+f"(c[3])
        : "r"(a[0]), "r"(a[1]), "r"(a[2]), "r"(a[3]), "r"(b[0]), "r"(b[1]));
}
__device__ __forceinline__ void mma_tf32(float* c, const uint32_t* a, const uint32_t* b) {
    asm volatile("mma.sync.aligned.m16n8k8.row.col.f32.tf32.tf32.f32 "
        "{%0,%1,%2,%3}, {%4,%5,%6,%7}, {%8,%9}, {%0,%1,%2,%3};"
        : "+f"(c[0]), "+f"(c[1]), "+f"(c[2]), "+f"(c[3])
        : "r"(a[0]), "r"(a[1]), "r"(a[2]), "r"(a[3]), "r"(b[0]), "r"(b[1]));
}
__device__ __forceinline__ float tf32_rna(float x) {
    uint32_t u;
    asm("cvt.rna.tf32.f32 %0, %1;" : "=r"(u) : "f"(x));
    return __uint_as_float(u);
}

// ---------------------------------------------------------------------------
// Split conversion kernels (fp32 -> hi/lo bf16)
// ---------------------------------------------------------------------------
__global__ void split2_kernel(const float* __restrict__ x,
                              __nv_bfloat162* __restrict__ h,
                              __nv_bfloat162* __restrict__ l, int n2)
{
    int i = blockIdx.x * blockDim.x + threadIdx.x;
    if (i < n2) {
        float2 v = ((const float2*)x)[i];
        __nv_bfloat16 h0 = __float2bfloat16(v.x);
        __nv_bfloat16 h1 = __float2bfloat16(v.y);
        __nv_bfloat16 l0 = __float2bfloat16(v.x - __bfloat162float(h0));
        __nv_bfloat16 l1 = __float2bfloat16(v.y - __bfloat162float(h1));
        h[i] = __halves2bfloat162(h0, h1);
        l[i] = __halves2bfloat162(l0, l1);
    }
}

// Transpose + split: W[k][n] (1024x1024 fp32) -> hT/lT[n][k] bf16
__global__ void tsplit_kernel(const float* __restrict__ W,
                              __nv_bfloat16* __restrict__ hT,
                              __nv_bfloat16* __restrict__ lT)
{
    __shared__ float t[32][33];
    const int tx = threadIdx.x, ty = threadIdx.y;   // 32 x 8
    const int n0 = blockIdx.x * 32, k0 = blockIdx.y * 32;
#pragma unroll
    for (int r = 0; r < 4; ++r)
        t[ty + 8*r][tx] = W[(k0 + ty + 8*r) * DM + n0 + tx];
    __syncthreads();
#pragma unroll
    for (int r = 0; r < 4; ++r) {
        const int n = n0 + ty + 8*r;
        const float v = t[tx][ty + 8*r];
        __nv_bfloat16 h = __float2bfloat16(v);
        __nv_bfloat16 l = __float2bfloat16(v - __bfloat162float(h));
        hT[n * DM + k0 + tx] = h;
        lT[n * DM + k0 + tx] = l;
    }
}

// ---------------------------------------------------------------------------
// mma.sync bf16x3 GEMM (unchanged; optional tf32 output rounding)
// ---------------------------------------------------------------------------
#define BK 32
#define RS 40
#define TILE_BYTES (128*RS*2)
#define STAGE_BYTES (4*TILE_BYTES)
#define GEMM_SMEM (2*STAGE_BYTES)
#define NCHUNK (DM/BK)

__global__ __launch_bounds__(256) void gemm_mma_kernel(
    const __nv_bfloat16* __restrict__ Ahp, const __nv_bfloat16* __restrict__ Alp,
    const __nv_bfloat16* __restrict__ BhT, const __nv_bfloat16* __restrict__ BlT,
    const float* __restrict__ bias, float* __restrict__ C, int rnd_tf32)
{
    extern __shared__ char smem[];
    const uint32_t sbase = smem_u32(smem);
    const int tid  = threadIdx.x;
    const int wid  = tid >> 5;
    const int lane = tid & 31;
    const int m0 = blockIdx.x * 128;
    const int n0 = blockIdx.y * 128;
    const int wm = (wid >> 1) * 32;
    const int wn = (wid & 1) * 64;

    const int lrow = tid >> 1;
    const int lch  = (tid & 1) * 2;
    const size_t gA = (size_t)(m0 + lrow) * DM;
    const size_t gB = (size_t)(n0 + lrow) * DM;

    auto load_stage = [&](int c, int s) {
        const uint32_t st = sbase + s * STAGE_BYTES;
        const int k0 = c * BK + lch * 8;
        const uint32_t so = lrow * (RS*2) + lch * 16;
        cpa16(st + so,                        Ahp + gA + k0);
        cpa16(st + so + 16,                   Ahp + gA + k0 + 8);
        cpa16(st + TILE_BYTES   + so,         Alp + gA + k0);
        cpa16(st + TILE_BYTES   + so + 16,    Alp + gA + k0 + 8);
        cpa16(st + 2*TILE_BYTES + so,         BhT + gB + k0);
        cpa16(st + 2*TILE_BYTES + so + 16,    BhT + gB + k0 + 8);
        cpa16(st + 3*TILE_BYTES + so,         BlT + gB + k0);
        cpa16(st + 3*TILE_BYTES + so + 16,    BlT + gB + k0 + 8);
        asm volatile("cp.async.commit_group;" ::: "memory");
    };

    float acc[2][8][4];
#pragma unroll
    for (int mt = 0; mt < 2; ++mt)
#pragma unroll
        for (int nt = 0; nt < 8; ++nt)
#pragma unroll
            for (int j = 0; j < 4; ++j) acc[mt][nt][j] = 0.f;

    load_stage(0, 0);
    load_stage(1, 1);

    const int a_row  = (lane & 15);
    const int a_colb = (lane & 16) ? 16 : 0;
    const int b_row  = ((lane & 16) ? 8 : 0) + (lane & 7);
    const int b_colb = (lane & 8) ? 16 : 0;

    for (int c = 0; c < NCHUNK; ++c) {
        if (c < NCHUNK - 1) asm volatile("cp.async.wait_group 1;" ::: "memory");
        else                asm volatile("cp.async.wait_group 0;" ::: "memory");
        __syncthreads();
        const uint32_t st = sbase + (c & 1) * STAGE_BYTES;
#pragma unroll
        for (int k16 = 0; k16 < 2; ++k16) {
            uint32_t ah[2][4], al[2][4], bh[16], bl[16];
#pragma unroll
            for (int mt = 0; mt < 2; ++mt) {
                const uint32_t a0 = st + (wm + mt*16 + a_row) * (RS*2)
                                       + k16*32 + a_colb;
                ldsm4(ah[mt], a0);
                ldsm4(al[mt], a0 + TILE_BYTES);
            }
#pragma unroll
            for (int p = 0; p < 4; ++p) {
                const uint32_t b0 = st + 2*TILE_BYTES
                                  + (wn + p*16 + b_row) * (RS*2)
                                  + k16*32 + b_colb;
                ldsm4(&bh[4*p], b0);
                ldsm4(&bl[4*p], b0 + TILE_BYTES);
            }
#pragma unroll
            for (int mt = 0; mt < 2; ++mt)
#pragma unroll
                for (int nt = 0; nt < 8; ++nt) {
                    mma16816(acc[mt][nt], ah[mt], &bh[nt*2]);
                    mma16816(acc[mt][nt], ah[mt], &bl[nt*2]);
                    mma16816(acc[mt][nt], al[mt], &bh[nt*2]);
                }
        }
        __syncthreads();
        if (c + 2 < NCHUNK) load_stage(c + 2, c & 1);
    }

    const int er = lane >> 2;
    const int ec = (lane & 3) * 2;
#pragma unroll
    for (int mt = 0; mt < 2; ++mt) {
        const int row = m0 + wm + mt*16 + er;
#pragma unroll
        for (int nt = 0; nt < 8; ++nt) {
            const int col = n0 + wn + nt*8 + ec;
            const float b0 = bias[col], b1 = bias[col + 1];
            float2 v0 = { acc[mt][nt][0] + b0, acc[mt][nt][1] + b1 };
            float2 v1 = { acc[mt][nt][2] + b0, acc[mt][nt][3] + b1 };
            if (rnd_tf32) {
                v0.x = tf32_rna(v0.x); v0.y = tf32_rna(v0.y);
                v1.x = tf32_rna(v1.x); v1.y = tf32_rna(v1.y);
            }
            *(float2*)(C + (size_t)row * DM + col)       = v0;
            *(float2*)(C + (size_t)(row + 8) * DM + col) = v1;
        }
    }
}

// ---------------------------------------------------------------------------
// tf32 mma.sync flash attention, v2:
//   - no P smem slab (shfl-based C-frag -> A-frag transpose)
//   - V smem XOR-rotated (conflict-free PV B-frag loads)
//   - 2 CTAs/SM (67.6KB smem, <=128 regs)
//   - log2-domain softmax (exp2f)
//   - epilogue emits bf16 hi/lo directly for the output projection
// ---------------------------------------------------------------------------
#define SPK 68
#define KTILE_F (64*SPK)                 // K tile floats
#define VTILE_F (64*64)                  // V tile floats (rotated, stride 64)
#define ATT_SMEM ((2*KTILE_F + 2*VTILE_F) * 4)   // 67,584 B
#define NIT (SL/64)                      // 32

__global__ __launch_bounds__(256, 2) void attn_mma_kernel(
    const float* __restrict__ Qp, const float* __restrict__ Kp,
    const float* __restrict__ Vp,
    __nv_bfloat16* __restrict__ Oh, __nv_bfloat16* __restrict__ Ol)
{
    extern __shared__ float fsm[];
    float* KsB = fsm;                    // [2][64][SPK]
    float* VsB = fsm + 2*KTILE_F;        // [2][64][64] rotated
    const uint32_t sb = smem_u32(fsm);
    const uint32_t sbV = sb + 2*KTILE_F*4;

    const int tid = threadIdx.x, wid = tid >> 5, lane = tid & 31;
    const int g = lane >> 2, tg = lane & 3;
    const int hb = blockIdx.y;
    const size_t base = (size_t)(hb & 1) * SL * DM + (size_t)(hb >> 1) * 64;
    const int q0 = blockIdx.x * 128;

    // ---- Q A-fragments, scaled by 0.125*log2(e), re-rounded to tf32 --------
    const float QSC = 0.125f * 1.4426950408889634f;
    uint32_t aq[8][4];
    {
        const float* Qr0 = Qp + base + (size_t)(q0 + wid*16 + g) * DM;
        const float* Qr1 = Qr0 + (size_t)8 * DM;
#pragma unroll
        for (int kk = 0; kk < 8; ++kk) {
            aq[kk][0] = __float_as_uint(tf32_rna(Qr0[kk*8 + tg]     * QSC));
            aq[kk][1] = __float_as_uint(tf32_rna(Qr1[kk*8 + tg]     * QSC));
            aq[kk][2] = __float_as_uint(tf32_rna(Qr0[kk*8 + tg + 4] * QSC));
            aq[kk][3] = __float_as_uint(tf32_rna(Qr1[kk*8 + tg + 4] * QSC));
        }
    }

    // ---- KV loader: thread t -> row t/4, four 16B chunks -------------------
    const int l_row = tid >> 2;          // 0..63
    const int l_c0  = (tid & 3) * 16;    // float col base
    const int l_rot = 8 * (l_row & 7);   // V rotation
    auto loadKV = [&](int it, int s) {
        const float* Kg = Kp + base + (size_t)(it*64 + l_row) * DM + l_c0;
        const float* Vg = Vp + base + (size_t)(it*64 + l_row) * DM + l_c0;
        const uint32_t kd = sb  + ((s*64 + l_row) * SPK + l_c0) * 4;
        const uint32_t vrow = sbV + ((s*64 + l_row) * 64) * 4;
#pragma unroll
        for (int cc = 0; cc < 4; ++cc) {
            cpa16(kd + cc*16, Kg + cc*4);
            cpa16(vrow + (((l_c0 + 4*cc + l_rot) & 63) * 4), Vg + cc*4);
        }
        asm volatile("cp.async.commit_group;" ::: "memory");
    };

    float acc[8][4];
#pragma unroll
    for (int j = 0; j < 8; ++j)
#pragma unroll
        for (int i = 0; i < 4; ++i) acc[j][i] = 0.f;
    float m0 = -INFINITY, m1 = -INFINITY, l0 = 0.f, l1 = 0.f;

    loadKV(0, 0);
    loadKV(1, 1);

    const int srcA = (lane & 28) | (tg >> 1);  // 4g + (t>>1)
    const bool oddt = (tg & 1);

    for (int it = 0; it < NIT; ++it) {
        const int s = it & 1;
        if (it < NIT - 1) asm volatile("cp.async.wait_group 1;" ::: "memory");
        else              asm volatile("cp.async.wait_group 0;" ::: "memory");
        __syncthreads();
        const float* Kt = KsB + s * KTILE_F;
        const float* Vt = VsB + s * VTILE_F;

        // ---- S = Q @ K^T (64 cols, log2-scaled) ----
        float sc[8][4];
#pragma unroll
        for (int j = 0; j < 8; ++j)
#pragma unroll
            for (int i = 0; i < 4; ++i) sc[j][i] = 0.f;
#pragma unroll
        for (int kk = 0; kk < 8; ++kk) {
#pragma unroll
            for (int j = 0; j < 8; ++j) {
                uint32_t bv[2];
                bv[0] = __float_as_uint(Kt[(8*j + g) * SPK + kk*8 + tg]);
                bv[1] = __float_as_uint(Kt[(8*j + g) * SPK + kk*8 + tg + 4]);
                mma_tf32(sc[j], aq[kk], bv);
            }
        }

        // ---- online softmax (base-2) ----
        float mx0 = -INFINITY, mx1 = -INFINITY;
#pragma unroll
        for (int j = 0; j < 8; ++j) {
            mx0 = fmaxf(mx0, fmaxf(sc[j][0], sc[j][1]));
            mx1 = fmaxf(mx1, fmaxf(sc[j][2], sc[j][3]));
        }
        mx0 = fmaxf(mx0, __shfl_xor_sync(0xffffffffu, mx0, 1));
        mx0 = fmaxf(mx0, __shfl_xor_sync(0xffffffffu, mx0, 2));
        mx1 = fmaxf(mx1, __shfl_xor_sync(0xffffffffu, mx1, 1));
        mx1 = fmaxf(mx1, __shfl_xor_sync(0xffffffffu, mx1, 2));

        const float mn0 = fmaxf(m0, mx0), mn1 = fmaxf(m1, mx1);
        const float c0 = exp2f(m0 - mn0), c1 = exp2f(m1 - mn1);
        m0 = mn0; m1 = mn1;
        float rs0 = 0.f, rs1 = 0.f;
#pragma unroll
        for (int j = 0; j < 8; ++j) {
            sc[j][0] = exp2f(sc[j][0] - mn0);
            sc[j][1] = exp2f(sc[j][1] - mn0);
            sc[j][2] = exp2f(sc[j][2] - mn1);
            sc[j][3] = exp2f(sc[j][3] - mn1);
            rs0 += sc[j][0] + sc[j][1];
            rs1 += sc[j][2] + sc[j][3];
            sc[j][0] = tf32_rna(sc[j][0]);
            sc[j][1] = tf32_rna(sc[j][1]);
            sc[j][2] = tf32_rna(sc[j][2]);
            sc[j][3] = tf32_rna(sc[j][3]);
        }
        rs0 += __shfl_xor_sync(0xffffffffu, rs0, 1);
        rs0 += __shfl_xor_sync(0xffffffffu, rs0, 2);
        rs1 += __shfl_xor_sync(0xffffffffu, rs1, 1);
        rs1 += __shfl_xor_sync(0xffffffffu, rs1, 2);
        l0 = l0 * c0 + rs0;
        l1 = l1 * c1 + rs1;
#pragma unroll
        for (int j = 0; j < 8; ++j) {
            acc[j][0] *= c0; acc[j][1] *= c0;
            acc[j][2] *= c1; acc[j][3] *= c1;
        }

        // ---- O += P @ V  (A-frags via shuffle transpose of sc) ----
#pragma unroll
        for (int kk = 0; kk < 8; ++kk) {
            float e00 = __shfl_sync(0xffffffffu, sc[kk][0], srcA);
            float e01 = __shfl_sync(0xffffffffu, sc[kk][1], srcA);
            float e10 = __shfl_sync(0xffffffffu, sc[kk][2], srcA);
            float e11 = __shfl_sync(0xffffffffu, sc[kk][3], srcA);
            float f00 = __shfl_sync(0xffffffffu, sc[kk][0], srcA + 2);
            float f01 = __shfl_sync(0xffffffffu, sc[kk][1], srcA + 2);
            float f10 = __shfl_sync(0xffffffffu, sc[kk][2], srcA + 2);
            float f11 = __shfl_sync(0xffffffffu, sc[kk][3], srcA + 2);
            uint32_t ap[4];
            ap[0] = __float_as_uint(oddt ? e01 : e00);  // row g,   k t
            ap[1] = __float_as_uint(oddt ? e11 : e10);  // row g+8, k t
            ap[2] = __float_as_uint(oddt ? f01 : f00);  // row g,   k t+4
            ap[3] = __float_as_uint(oddt ? f11 : f10);  // row g+8, k t+4

            const int r0 = kk*8 + tg;        // V row for b0
            const int r1 = r0 + 4;           // V row for b1
            const int rot0 = 8 * (r0 & 7), rot1 = 8 * (r1 & 7);
#pragma unroll
            for (int j = 0; j < 8; ++j) {
                uint32_t bv[2];
                bv[0] = __float_as_uint(Vt[r0 * 64 + ((8*j + g + rot0) & 63)]);
                bv[1] = __float_as_uint(Vt[r1 * 64 + ((8*j + g + rot1) & 63)]);
                mma_tf32(acc[j], ap, bv);
            }
        }

        __syncthreads();
        if (it + 2 < NIT) loadKV(it + 2, s);
    }

    // ---- epilogue: normalize, split to bf16 hi/lo, store -------------------
    const float i0 = 1.f / l0, i1 = 1.f / l1;
    const size_t ro0 = base + (size_t)(q0 + wid*16 + g) * DM;
    const size_t ro1 = ro0 + (size_t)8 * DM;
#pragma unroll
    for (int j = 0; j < 8; ++j) {
        const int col = 8*j + 2*tg;
        float o00 = acc[j][0] * i0, o01 = acc[j][1] * i0;
        float o10 = acc[j][2] * i1, o11 = acc[j][3] * i1;
        __nv_bfloat16 h00 = __float2bfloat16(o00), h01 = __float2bfloat16(o01);
        __nv_bfloat16 h10 = __float2bfloat16(o10), h11 = __float2bfloat16(o11);
        __nv_bfloat16 q00 = __float2bfloat16(o00 - __bfloat162float(h00));
        __nv_bfloat16 q01 = __float2bfloat16(o01 - __bfloat162float(h01));
        __nv_bfloat16 q10 = __float2bfloat16(o10 - __bfloat162float(h10));
        __nv_bfloat16 q11 = __float2bfloat16(o11 - __bfloat162float(h11));
        *(__nv_bfloat162*)(Oh + ro0 + col) = __halves2bfloat162(h00, h01);
        *(__nv_bfloat162*)(Oh + ro1 + col) = __halves2bfloat162(h10, h11);
        *(__nv_bfloat162*)(Ol + ro0 + col) = __halves2bfloat162(q00, q01);
        *(__nv_bfloat162*)(Ol + ro1 + col) = __halves2bfloat162(q10, q11);
    }
}

// ---------------------------------------------------------------------------
extern "C" void kernel_launch(void* const* d_in, const int* in_sizes, int n_in,
                              void* d_out, int out_size)
{
    const float* q   = (const float*)d_in[0];
    const float* k   = (const float*)d_in[1];
    const float* v   = (const float*)d_in[2];
    const float* w_q = (const float*)d_in[3];
    const float* b_q = (const float*)d_in[4];
    const float* w_k = (const float*)d_in[5];
    const float* b_k = (const float*)d_in[6];
    const float* w_v = (const float*)d_in[7];
    const float* b_v = (const float*)d_in[8];
    const float* w_o = (const float*)d_in[9];
    const float* b_o = (const float*)d_in[10];
    float* out = (float*)d_out;

    cudaFuncSetAttribute(gemm_mma_kernel,
                         cudaFuncAttributeMaxDynamicSharedMemorySize, GEMM_SMEM);
    cudaFuncSetAttribute(attn_mma_kernel,
                         cudaFuncAttributeMaxDynamicSharedMemorySize, ATT_SMEM);

    float *gq, *gk, *gv;
    cudaGetSymbolAddress((void**)&gq,  g_q);
    cudaGetSymbolAddress((void**)&gk,  g_k);
    cudaGetSymbolAddress((void**)&gv,  g_v);
    __nv_bfloat16 *qh,*ql,*kh,*kl,*vh,*vl,*aoh,*aol;
    __nv_bfloat16 *wqh,*wql,*wkh,*wkl,*wvh,*wvl,*woh,*wol;
    cudaGetSymbolAddress((void**)&qh,  g_qh);  cudaGetSymbolAddress((void**)&ql,  g_ql);
    cudaGetSymbolAddress((void**)&kh,  g_kh);  cudaGetSymbolAddress((void**)&kl,  g_kl);
    cudaGetSymbolAddress((void**)&vh,  g_vh);  cudaGetSymbolAddress((void**)&vl,  g_vl);
    cudaGetSymbolAddress((void**)&aoh, g_aoh); cudaGetSymbolAddress((void**)&aol, g_aol);
    cudaGetSymbolAddress((void**)&wqh, g_wqh); cudaGetSymbolAddress((void**)&wql, g_wql);
    cudaGetSymbolAddress((void**)&wkh, g_wkh); cudaGetSymbolAddress((void**)&wkl, g_wkl);
    cudaGetSymbolAddress((void**)&wvh, g_wvh); cudaGetSymbolAddress((void**)&wvl, g_wvl);
    cudaGetSymbolAddress((void**)&woh, g_woh); cudaGetSymbolAddress((void**)&wol, g_wol);

    const int n2 = MR * DM / 2;
    const dim3 sgrid((n2 + 255) / 256), sblk(256);
    split2_kernel<<<sgrid, sblk>>>(q, (__nv_bfloat162*)qh, (__nv_bfloat162*)ql, n2);
    split2_kernel<<<sgrid, sblk>>>(k, (__nv_bfloat162*)kh, (__nv_bfloat162*)kl, n2);
    split2_kernel<<<sgrid, sblk>>>(v, (__nv_bfloat162*)vh, (__nv_bfloat162*)vl, n2);

    const dim3 tgrid(DM/32, DM/32), tblk(32, 8);
    tsplit_kernel<<<tgrid, tblk>>>(w_q, wqh, wql);
    tsplit_kernel<<<tgrid, tblk>>>(w_k, wkh, wkl);
    tsplit_kernel<<<tgrid, tblk>>>(w_v, wvh, wvl);
    tsplit_kernel<<<tgrid, tblk>>>(w_o, woh, wol);

    const dim3 ggrid(MR/128, DM/128);    // (32, 8)
    gemm_mma_kernel<<<ggrid, 256, GEMM_SMEM>>>(qh, ql, wqh, wql, b_q, gq, 1);
    gemm_mma_kernel<<<ggrid, 256, GEMM_SMEM>>>(kh, kl, wkh, wkl, b_k, gk, 1);
    gemm_mma_kernel<<<ggrid, 256, GEMM_SMEM>>>(vh, vl, wvh, wvl, b_v, gv, 1);

    attn_mma_kernel<<<dim3(SL/128, NH*BSZ), 256, ATT_SMEM>>>(gq, gk, gv, aoh, aol);

    gemm_mma_kernel<<<ggrid, 256, GEMM_SMEM>>>(aoh, aol, woh, wol, b_o, out, 0);
}

// round 8
// speedup vs baseline: 2.7688x; 1.0167x over previous
#include <cuda_runtime.h>
#include <math.h>
#include <stdint.h>

#define DM 1024
#define BSZ 2
#define SL  2048
#define NH  16
#define MR  (BSZ*SL)   // 4096 rows for projection GEMMs

// ---------------------------------------------------------------------------
// Scratch (device globals: allocation-free per harness rules)
// ---------------------------------------------------------------------------
__device__ float g_q [MR*DM];     // projected Q (tf32-rounded)
__device__ float g_k [MR*DM];
__device__ float g_v [MR*DM];
__device__ float g_ao[MR*DM];     // attention output (tf32-rounded)
__device__ float g_qr[MR*DM];     // tf32-rounded raw inputs
__device__ float g_kr[MR*DM];
__device__ float g_vr[MR*DM];
__device__ float g_wqt[DM*DM];    // transposed + tf32-rounded weights [n][k]
__device__ float g_wkt[DM*DM];
__device__ float g_wvt[DM*DM];
__device__ float g_wot[DM*DM];

// ---------------------------------------------------------------------------
// Helpers (family-portable PTX only: cp.async, mma.sync)
// ---------------------------------------------------------------------------
__device__ __forceinline__ uint32_t smem_u32(const void* p) {
    uint32_t a;
    asm("{ .reg .u64 t; cvta.to.shared.u64 t, %1; cvt.u32.u64 %0, t; }"
        : "=r"(a) : "l"(p));
    return a;
}
__device__ __forceinline__ void cpa16(uint32_t dst, const void* src) {
    asm volatile("cp.async.cg.shared.global [%0], [%1], 16;" :: "r"(dst), "l"(src));
}
__device__ __forceinline__ void mma_tf32(float* c, const uint32_t* a, const uint32_t* b) {
    asm volatile("mma.sync.aligned.m16n8k8.row.col.f32.tf32.tf32.f32 "
        "{%0,%1,%2,%3}, {%4,%5,%6,%7}, {%8,%9}, {%0,%1,%2,%3};"
        : "+f"(c[0]), "+f"(c[1]), "+f"(c[2]), "+f"(c[3])
        : "r"(a[0]), "r"(a[1]), "r"(a[2]), "r"(a[3]), "r"(b[0]), "r"(b[1]));
}
__device__ __forceinline__ float tf32_rna(float x) {
    uint32_t u;
    asm("cvt.rna.tf32.f32 %0, %1;" : "=r"(u) : "f"(x));
    return __uint_as_float(u);
}

// ---------------------------------------------------------------------------
// Elementwise tf32 rounding (float4-vectorized)
// ---------------------------------------------------------------------------
__global__ void round_tf32_kernel(const float4* __restrict__ x,
                                  float4* __restrict__ y, int n4)
{
    int i = blockIdx.x * blockDim.x + threadIdx.x;
    if (i < n4) {
        float4 v = x[i];
        v.x = tf32_rna(v.x); v.y = tf32_rna(v.y);
        v.z = tf32_rna(v.z); v.w = tf32_rna(v.w);
        y[i] = v;
    }
}

// Transpose + tf32-round: W[k][n] -> WT[n][k]
__global__ void trt_kernel(const float* __restrict__ W, float* __restrict__ WT)
{
    __shared__ float t[32][33];
    const int tx = threadIdx.x, ty = threadIdx.y;   // 32 x 8
    const int n0 = blockIdx.x * 32, k0 = blockIdx.y * 32;
#pragma unroll
    for (int r = 0; r < 4; ++r)
        t[ty + 8*r][tx] = W[(k0 + ty + 8*r) * DM + n0 + tx];
    __syncthreads();
#pragma unroll
    for (int r = 0; r < 4; ++r)
        WT[(n0 + ty + 8*r) * DM + k0 + tx] = tf32_rna(t[tx][ty + 8*r]);
}

// ---------------------------------------------------------------------------
// Single-pass tf32 mma.sync GEMM: C[4096,1024] = A @ WT^T + bias
//   Block 128x128, BK=32, 256 threads (8 warps 4m x 2n), warp tile 32x64.
//   fp32 operands in smem, row stride 36 floats (==4 mod 32 -> all fragment
//   LDS patterns hit bank (4g+tg) mod 32: a lane permutation, conflict-free).
//   Double-buffered cp.async. 73.7KB smem, 2 CTAs/SM.
// ---------------------------------------------------------------------------
#define GRS 36
#define GTILE_F (128*GRS)
#define GSTAGE_F (2*GTILE_F)
#define GEMM_SMEM (2*GSTAGE_F*4)    // 73728 B
#define GNCH (DM/32)                // 32

__global__ __launch_bounds__(256, 2) void gemm_tf32_kernel(
    const float* __restrict__ A, const float* __restrict__ BT,
    const float* __restrict__ bias, float* __restrict__ C, int rnd)
{
    extern __shared__ float gs[];
    const uint32_t sbase = smem_u32(gs);
    const int tid  = threadIdx.x;
    const int wid  = tid >> 5;
    const int lane = tid & 31;
    const int g = lane >> 2, tg = lane & 3;
    const int m0 = blockIdx.x * 128;
    const int n0 = blockIdx.y * 128;
    const int wm = (wid >> 1) * 32;
    const int wn = (wid & 1) * 64;

    const int lrow = tid >> 1;           // 0..127
    const int lcf  = (tid & 1) * 16;     // float col base (16 floats per thread)
    const size_t gA = (size_t)(m0 + lrow) * DM;
    const size_t gB = (size_t)(n0 + lrow) * DM;

    auto load_stage = [&](int c, int s) {
        const uint32_t stA = sbase + (s * GSTAGE_F) * 4;
        const uint32_t stB = stA + GTILE_F * 4;
        const int k0 = c * 32 + lcf;
        const uint32_t so = (lrow * GRS + lcf) * 4;
#pragma unroll
        for (int cc = 0; cc < 4; ++cc) {
            cpa16(stA + so + cc*16, A  + gA + k0 + cc*4);
            cpa16(stB + so + cc*16, BT + gB + k0 + cc*4);
        }
        asm volatile("cp.async.commit_group;" ::: "memory");
    };

    float acc[2][8][4];
#pragma unroll
    for (int mt = 0; mt < 2; ++mt)
#pragma unroll
        for (int nt = 0; nt < 8; ++nt)
#pragma unroll
            for (int j = 0; j < 4; ++j) acc[mt][nt][j] = 0.f;

    load_stage(0, 0);
    load_stage(1, 1);

    for (int c = 0; c < GNCH; ++c) {
        if (c < GNCH - 1) asm volatile("cp.async.wait_group 1;" ::: "memory");
        else              asm volatile("cp.async.wait_group 0;" ::: "memory");
        __syncthreads();
        const float* As = gs + (c & 1) * GSTAGE_F;
        const float* Bs = As + GTILE_F;
#pragma unroll
        for (int kk = 0; kk < 4; ++kk) {
            uint32_t a[2][4];
#pragma unroll
            for (int mt = 0; mt < 2; ++mt) {
                const int rb = wm + mt*16;
                a[mt][0] = __float_as_uint(As[(rb + g    ) * GRS + kk*8 + tg]);
                a[mt][1] = __float_as_uint(As[(rb + g + 8) * GRS + kk*8 + tg]);
                a[mt][2] = __float_as_uint(As[(rb + g    ) * GRS + kk*8 + tg + 4]);
                a[mt][3] = __float_as_uint(As[(rb + g + 8) * GRS + kk*8 + tg + 4]);
            }
#pragma unroll
            for (int nt = 0; nt < 8; ++nt) {
                const int n = wn + nt*8 + g;
                uint32_t b[2];
                b[0] = __float_as_uint(Bs[n * GRS + kk*8 + tg]);
                b[1] = __float_as_uint(Bs[n * GRS + kk*8 + tg + 4]);
                mma_tf32(acc[0][nt], a[0], b);
                mma_tf32(acc[1][nt], a[1], b);
            }
        }
        __syncthreads();
        if (c + 2 < GNCH) load_stage(c + 2, c & 1);
    }

    const int er = lane >> 2;
    const int ec = (lane & 3) * 2;
#pragma unroll
    for (int mt = 0; mt < 2; ++mt) {
        const int row = m0 + wm + mt*16 + er;
#pragma unroll
        for (int nt = 0; nt < 8; ++nt) {
            const int col = n0 + wn + nt*8 + ec;
            const float b0 = bias[col], b1 = bias[col + 1];
            float2 v0 = { acc[mt][nt][0] + b0, acc[mt][nt][1] + b1 };
            float2 v1 = { acc[mt][nt][2] + b0, acc[mt][nt][3] + b1 };
            if (rnd) {
                v0.x = tf32_rna(v0.x); v0.y = tf32_rna(v0.y);
                v1.x = tf32_rna(v1.x); v1.y = tf32_rna(v1.y);
            }
            *(float2*)(C + (size_t)row * DM + col)       = v0;
            *(float2*)(C + (size_t)(row + 8) * DM + col) = v1;
        }
    }
}

// ---------------------------------------------------------------------------
// tf32 mma.sync flash attention (v2, unchanged core); epilogue now writes
// tf32-rounded fp32 for the output projection.
// ---------------------------------------------------------------------------
#define SPK 68
#define KTILE_F (64*SPK)
#define VTILE_F (64*64)
#define ATT_SMEM ((2*KTILE_F + 2*VTILE_F) * 4)   // 67,584 B
#define NIT (SL/64)

__global__ __launch_bounds__(256, 2) void attn_mma_kernel(
    const float* __restrict__ Qp, const float* __restrict__ Kp,
    const float* __restrict__ Vp, float* __restrict__ Ao)
{
    extern __shared__ float fsm[];
    float* KsB = fsm;
    float* VsB = fsm + 2*KTILE_F;
    const uint32_t sb = smem_u32(fsm);
    const uint32_t sbV = sb + 2*KTILE_F*4;

    const int tid = threadIdx.x, wid = tid >> 5, lane = tid & 31;
    const int g = lane >> 2, tg = lane & 3;
    const int hb = blockIdx.y;
    const size_t base = (size_t)(hb & 1) * SL * DM + (size_t)(hb >> 1) * 64;
    const int q0 = blockIdx.x * 128;

    const float QSC = 0.125f * 1.4426950408889634f;
    uint32_t aq[8][4];
    {
        const float* Qr0 = Qp + base + (size_t)(q0 + wid*16 + g) * DM;
        const float* Qr1 = Qr0 + (size_t)8 * DM;
#pragma unroll
        for (int kk = 0; kk < 8; ++kk) {
            aq[kk][0] = __float_as_uint(tf32_rna(Qr0[kk*8 + tg]     * QSC));
            aq[kk][1] = __float_as_uint(tf32_rna(Qr1[kk*8 + tg]     * QSC));
            aq[kk][2] = __float_as_uint(tf32_rna(Qr0[kk*8 + tg + 4] * QSC));
            aq[kk][3] = __float_as_uint(tf32_rna(Qr1[kk*8 + tg + 4] * QSC));
        }
    }

    const int l_row = tid >> 2;
    const int l_c0  = (tid & 3) * 16;
    const int l_rot = 8 * (l_row & 7);
    auto loadKV = [&](int it, int s) {
        const float* Kg = Kp + base + (size_t)(it*64 + l_row) * DM + l_c0;
        const float* Vg = Vp + base + (size_t)(it*64 + l_row) * DM + l_c0;
        const uint32_t kd = sb  + ((s*64 + l_row) * SPK + l_c0) * 4;
        const uint32_t vrow = sbV + ((s*64 + l_row) * 64) * 4;
#pragma unroll
        for (int cc = 0; cc < 4; ++cc) {
            cpa16(kd + cc*16, Kg + cc*4);
            cpa16(vrow + (((l_c0 + 4*cc + l_rot) & 63) * 4), Vg + cc*4);
        }
        asm volatile("cp.async.commit_group;" ::: "memory");
    };

    float acc[8][4];
#pragma unroll
    for (int j = 0; j < 8; ++j)
#pragma unroll
        for (int i = 0; i < 4; ++i) acc[j][i] = 0.f;
    float m0 = -INFINITY, m1 = -INFINITY, l0 = 0.f, l1 = 0.f;

    loadKV(0, 0);
    loadKV(1, 1);

    const int srcA = (lane & 28) | (tg >> 1);
    const bool oddt = (tg & 1);

    for (int it = 0; it < NIT; ++it) {
        const int s = it & 1;
        if (it < NIT - 1) asm volatile("cp.async.wait_group 1;" ::: "memory");
        else              asm volatile("cp.async.wait_group 0;" ::: "memory");
        __syncthreads();
        const float* Kt = KsB + s * KTILE_F;
        const float* Vt = VsB + s * VTILE_F;

        float sc[8][4];
#pragma unroll
        for (int j = 0; j < 8; ++j)
#pragma unroll
            for (int i = 0; i < 4; ++i) sc[j][i] = 0.f;
#pragma unroll
        for (int kk = 0; kk < 8; ++kk) {
#pragma unroll
            for (int j = 0; j < 8; ++j) {
                uint32_t bv[2];
                bv[0] = __float_as_uint(Kt[(8*j + g) * SPK + kk*8 + tg]);
                bv[1] = __float_as_uint(Kt[(8*j + g) * SPK + kk*8 + tg + 4]);
                mma_tf32(sc[j], aq[kk], bv);
            }
        }

        float mx0 = -INFINITY, mx1 = -INFINITY;
#pragma unroll
        for (int j = 0; j < 8; ++j) {
            mx0 = fmaxf(mx0, fmaxf(sc[j][0], sc[j][1]));
            mx1 = fmaxf(mx1, fmaxf(sc[j][2], sc[j][3]));
        }
        mx0 = fmaxf(mx0, __shfl_xor_sync(0xffffffffu, mx0, 1));
        mx0 = fmaxf(mx0, __shfl_xor_sync(0xffffffffu, mx0, 2));
        mx1 = fmaxf(mx1, __shfl_xor_sync(0xffffffffu, mx1, 1));
        mx1 = fmaxf(mx1, __shfl_xor_sync(0xffffffffu, mx1, 2));

        const float mn0 = fmaxf(m0, mx0), mn1 = fmaxf(m1, mx1);
        const float c0 = exp2f(m0 - mn0), c1 = exp2f(m1 - mn1);
        m0 = mn0; m1 = mn1;
        float rs0 = 0.f, rs1 = 0.f;
#pragma unroll
        for (int j = 0; j < 8; ++j) {
            sc[j][0] = exp2f(sc[j][0] - mn0);
            sc[j][1] = exp2f(sc[j][1] - mn0);
            sc[j][2] = exp2f(sc[j][2] - mn1);
            sc[j][3] = exp2f(sc[j][3] - mn1);
            rs0 += sc[j][0] + sc[j][1];
            rs1 += sc[j][2] + sc[j][3];
            sc[j][0] = tf32_rna(sc[j][0]);
            sc[j][1] = tf32_rna(sc[j][1]);
            sc[j][2] = tf32_rna(sc[j][2]);
            sc[j][3] = tf32_rna(sc[j][3]);
        }
        rs0 += __shfl_xor_sync(0xffffffffu, rs0, 1);
        rs0 += __shfl_xor_sync(0xffffffffu, rs0, 2);
        rs1 += __shfl_xor_sync(0xffffffffu, rs1, 1);
        rs1 += __shfl_xor_sync(0xffffffffu, rs1, 2);
        l0 = l0 * c0 + rs0;
        l1 = l1 * c1 + rs1;
#pragma unroll
        for (int j = 0; j < 8; ++j) {
            acc[j][0] *= c0; acc[j][1] *= c0;
            acc[j][2] *= c1; acc[j][3] *= c1;
        }

#pragma unroll
        for (int kk = 0; kk < 8; ++kk) {
            float e00 = __shfl_sync(0xffffffffu, sc[kk][0], srcA);
            float e01 = __shfl_sync(0xffffffffu, sc[kk][1], srcA);
            float e10 = __shfl_sync(0xffffffffu, sc[kk][2], srcA);
            float e11 = __shfl_sync(0xffffffffu, sc[kk][3], srcA);
            float f00 = __shfl_sync(0xffffffffu, sc[kk][0], srcA + 2);
            float f01 = __shfl_sync(0xffffffffu, sc[kk][1], srcA + 2);
            float f10 = __shfl_sync(0xffffffffu, sc[kk][2], srcA + 2);
            float f11 = __shfl_sync(0xffffffffu, sc[kk][3], srcA + 2);
            uint32_t ap[4];
            ap[0] = __float_as_uint(oddt ? e01 : e00);
            ap[1] = __float_as_uint(oddt ? e11 : e10);
            ap[2] = __float_as_uint(oddt ? f01 : f00);
            ap[3] = __float_as_uint(oddt ? f11 : f10);

            const int r0 = kk*8 + tg;
            const int r1 = r0 + 4;
            const int rot0 = 8 * (r0 & 7), rot1 = 8 * (r1 & 7);
#pragma unroll
            for (int j = 0; j < 8; ++j) {
                uint32_t bv[2];
                bv[0] = __float_as_uint(Vt[r0 * 64 + ((8*j + g + rot0) & 63)]);
                bv[1] = __float_as_uint(Vt[r1 * 64 + ((8*j + g + rot1) & 63)]);
                mma_tf32(acc[j], ap, bv);
            }
        }

        __syncthreads();
        if (it + 2 < NIT) loadKV(it + 2, s);
    }

    // ---- epilogue: normalize, tf32-round, store fp32 ----
    const float i0 = 1.f / l0, i1 = 1.f / l1;
    const size_t ro0 = base + (size_t)(q0 + wid*16 + g) * DM;
    const size_t ro1 = ro0 + (size_t)8 * DM;
#pragma unroll
    for (int j = 0; j < 8; ++j) {
        const int col = 8*j + 2*tg;
        float2 v0 = { tf32_rna(acc[j][0] * i0), tf32_rna(acc[j][1] * i0) };
        float2 v1 = { tf32_rna(acc[j][2] * i1), tf32_rna(acc[j][3] * i1) };
        *(float2*)(Ao + ro0 + col) = v0;
        *(float2*)(Ao + ro1 + col) = v1;
    }
}

// ---------------------------------------------------------------------------
extern "C" void kernel_launch(void* const* d_in, const int* in_sizes, int n_in,
                              void* d_out, int out_size)
{
    const float* q   = (const float*)d_in[0];
    const float* k   = (const float*)d_in[1];
    const float* v   = (const float*)d_in[2];
    const float* w_q = (const float*)d_in[3];
    const float* b_q = (const float*)d_in[4];
    const float* w_k = (const float*)d_in[5];
    const float* b_k = (const float*)d_in[6];
    const float* w_v = (const float*)d_in[7];
    const float* b_v = (const float*)d_in[8];
    const float* w_o = (const float*)d_in[9];
    const float* b_o = (const float*)d_in[10];
    float* out = (float*)d_out;

    cudaFuncSetAttribute(gemm_tf32_kernel,
                         cudaFuncAttributeMaxDynamicSharedMemorySize, GEMM_SMEM);
    cudaFuncSetAttribute(attn_mma_kernel,
                         cudaFuncAttributeMaxDynamicSharedMemorySize, ATT_SMEM);

    float *gq, *gk, *gv, *gao, *gqr, *gkr, *gvr;
    float *wqt, *wkt, *wvt, *wot;
    cudaGetSymbolAddress((void**)&gq,  g_q);
    cudaGetSymbolAddress((void**)&gk,  g_k);
    cudaGetSymbolAddress((void**)&gv,  g_v);
    cudaGetSymbolAddress((void**)&gao, g_ao);
    cudaGetSymbolAddress((void**)&gqr, g_qr);
    cudaGetSymbolAddress((void**)&gkr, g_kr);
    cudaGetSymbolAddress((void**)&gvr, g_vr);
    cudaGetSymbolAddress((void**)&wqt, g_wqt);
    cudaGetSymbolAddress((void**)&wkt, g_wkt);
    cudaGetSymbolAddress((void**)&wvt, g_wvt);
    cudaGetSymbolAddress((void**)&wot, g_wot);

    const int n4 = MR * DM / 4;
    const dim3 rgrid((n4 + 255) / 256), rblk(256);
    round_tf32_kernel<<<rgrid, rblk>>>((const float4*)q, (float4*)gqr, n4);
    round_tf32_kernel<<<rgrid, rblk>>>((const float4*)k, (float4*)gkr, n4);
    round_tf32_kernel<<<rgrid, rblk>>>((const float4*)v, (float4*)gvr, n4);

    const dim3 tgrid(DM/32, DM/32), tblk(32, 8);
    trt_kernel<<<tgrid, tblk>>>(w_q, wqt);
    trt_kernel<<<tgrid, tblk>>>(w_k, wkt);
    trt_kernel<<<tgrid, tblk>>>(w_v, wvt);
    trt_kernel<<<tgrid, tblk>>>(w_o, wot);

    const dim3 ggrid(MR/128, DM/128);    // (32, 8)
    gemm_tf32_kernel<<<ggrid, 256, GEMM_SMEM>>>(gqr, wqt, b_q, gq, 1);
    gemm_tf32_kernel<<<ggrid, 256, GEMM_SMEM>>>(gkr, wkt, b_k, gk, 1);
    gemm_tf32_kernel<<<ggrid, 256, GEMM_SMEM>>>(gvr, wvt, b_v, gv, 1);

    attn_mma_kernel<<<dim3(SL/128, NH*BSZ), 256, ATT_SMEM>>>(gq, gk, gv, gao);

    gemm_tf32_kernel<<<ggrid, 256, GEMM_SMEM>>>(gao, wot, b_o, out, 0);
}

// round 9
// speedup vs baseline: 5.9540x; 2.1504x over previous
#include <cuda_runtime.h>
#include <cuda_fp16.h>
#include <math.h>
#include <stdint.h>

#define DM 1024
#define BSZ 2
#define SL  2048
#define NH  16
#define MR  (BSZ*SL)

// ---------------------------------------------------------------------------
// Scratch (device globals: allocation-free per harness rules)
// ---------------------------------------------------------------------------
__device__ __half h_q [MR*DM];    // projected Q (pre-scaled by 0.125*log2e)
__device__ __half h_k [MR*DM];
__device__ __half h_v [MR*DM];
__device__ __half h_ao[MR*DM];    // attention output
__device__ __half h_qi[MR*DM];    // fp16-converted raw inputs
__device__ __half h_ki[MR*DM];
__device__ __half h_vi[MR*DM];
__device__ __half h_wq[DM*DM];    // transposed fp16 weights [n][k]
__device__ __half h_wk[DM*DM];
__device__ __half h_wv[DM*DM];
__device__ __half h_wo[DM*DM];

// ---------------------------------------------------------------------------
// Helpers (family-portable PTX: cp.async, ldmatrix, mma.sync)
// ---------------------------------------------------------------------------
__device__ __forceinline__ uint32_t smem_u32(const void* p) {
    uint32_t a;
    asm("{ .reg .u64 t; cvta.to.shared.u64 t, %1; cvt.u32.u64 %0, t; }"
        : "=r"(a) : "l"(p));
    return a;
}
__device__ __forceinline__ void cpa16(uint32_t dst, const void* src) {
    asm volatile("cp.async.cg.shared.global [%0], [%1], 16;" :: "r"(dst), "l"(src));
}
__device__ __forceinline__ void ldsm4(uint32_t* r, uint32_t addr) {
    asm volatile("ldmatrix.sync.aligned.m8n8.x4.shared.b16 {%0,%1,%2,%3}, [%4];"
        : "=r"(r[0]), "=r"(r[1]), "=r"(r[2]), "=r"(r[3]) : "r"(addr));
}
__device__ __forceinline__ void ldsm4t(uint32_t* r, uint32_t addr) {
    asm volatile("ldmatrix.sync.aligned.m8n8.x4.trans.shared.b16 {%0,%1,%2,%3}, [%4];"
        : "=r"(r[0]), "=r"(r[1]), "=r"(r[2]), "=r"(r[3]) : "r"(addr));
}
__device__ __forceinline__ void mma_f16(float* c, const uint32_t* a, const uint32_t* b) {
    asm volatile("mma.sync.aligned.m16n8k16.row.col.f32.f16.f16.f32 "
        "{%0,%1,%2,%3}, {%4,%5,%6,%7}, {%8,%9}, {%0,%1,%2,%3};"
        : "+f"(c[0]), "+f"(c[1]), "+f"(c[2]), "+f"(c[3])
        : "r"(a[0]), "r"(a[1]), "r"(a[2]), "r"(a[3]), "r"(b[0]), "r"(b[1]));
}
__device__ __forceinline__ uint32_t packh2(float a, float b) {
    __half2 h = __float22half2_rn(make_float2(a, b));
    return *(uint32_t*)&h;
}

// ---------------------------------------------------------------------------
// fp32 -> fp16 conversion (vectorized)
// ---------------------------------------------------------------------------
__global__ void tohalf_kernel(const float4* __restrict__ x,
                              uint2* __restrict__ y, int n4)
{
    int i = blockIdx.x * blockDim.x + threadIdx.x;
    if (i < n4) {
        float4 v = x[i];
        uint2 u;
        u.x = packh2(v.x, v.y);
        u.y = packh2(v.z, v.w);
        y[i] = u;
    }
}

// Transpose + fp16: W[k][n] -> WT[n][k] half
__global__ void trth_kernel(const float* __restrict__ W, __half* __restrict__ WT)
{
    __shared__ float t[32][33];
    const int tx = threadIdx.x, ty = threadIdx.y;   // 32 x 8
    const int n0 = blockIdx.x * 32, k0 = blockIdx.y * 32;
#pragma unroll
    for (int r = 0; r < 4; ++r)
        t[ty + 8*r][tx] = W[(k0 + ty + 8*r) * DM + n0 + tx];
    __syncthreads();
#pragma unroll
    for (int r = 0; r < 4; ++r)
        WT[(n0 + ty + 8*r) * DM + k0 + tx] = __float2half_rn(t[tx][ty + 8*r]);
}

// ---------------------------------------------------------------------------
// Single-pass fp16 mma.sync GEMM: C = (A @ WT^T + bias) * scale
//   Block 128x128, BK=32, 256 threads (8 warps 4m x 2n), warp tile 32x64.
//   Proven R2 ldmatrix skeleton; half tiles, rows padded to 80B.
//   Output: half (Ch) or fp32 (Cf).
// ---------------------------------------------------------------------------
#define RS 40                       // halves per smem row (80 B)
#define TILEB (128*RS*2)            // 10240 B
#define STAGEB (2*TILEB)            // A + B
#define GEMM_SMEM (2*STAGEB)        // 40960 B
#define NCH (DM/32)                 // 32

__global__ __launch_bounds__(256) void gemm_f16_kernel(
    const __half* __restrict__ A, const __half* __restrict__ BT,
    const float* __restrict__ bias, __half* __restrict__ Ch,
    float* __restrict__ Cf, float scale)
{
    extern __shared__ char smem[];
    const uint32_t sbase = smem_u32(smem);
    const int tid  = threadIdx.x;
    const int wid  = tid >> 5;
    const int lane = tid & 31;
    const int m0 = blockIdx.x * 128;
    const int n0 = blockIdx.y * 128;
    const int wm = (wid >> 1) * 32;
    const int wn = (wid & 1) * 64;

    const int lrow = tid >> 1;
    const int lk0  = (tid & 1) * 16;          // half col base
    const size_t gA = (size_t)(m0 + lrow) * DM;
    const size_t gB = (size_t)(n0 + lrow) * DM;

    auto load_stage = [&](int c, int s) {
        const uint32_t stA = sbase + s * STAGEB;
        const uint32_t stB = stA + TILEB;
        const int k0 = c * 32 + lk0;
        const uint32_t so = lrow * (RS*2) + lk0 * 2;
        cpa16(stA + so,      A  + gA + k0);
        cpa16(stA + so + 16, A  + gA + k0 + 8);
        cpa16(stB + so,      BT + gB + k0);
        cpa16(stB + so + 16, BT + gB + k0 + 8);
        asm volatile("cp.async.commit_group;" ::: "memory");
    };

    float acc[2][8][4];
#pragma unroll
    for (int mt = 0; mt < 2; ++mt)
#pragma unroll
        for (int nt = 0; nt < 8; ++nt)
#pragma unroll
            for (int j = 0; j < 4; ++j) acc[mt][nt][j] = 0.f;

    load_stage(0, 0);
    load_stage(1, 1);

    const int a_row  = (lane & 15);
    const int a_colb = (lane & 16) ? 16 : 0;
    const int b_row  = ((lane & 16) ? 8 : 0) + (lane & 7);
    const int b_colb = (lane & 8) ? 16 : 0;

    for (int c = 0; c < NCH; ++c) {
        if (c < NCH - 1) asm volatile("cp.async.wait_group 1;" ::: "memory");
        else             asm volatile("cp.async.wait_group 0;" ::: "memory");
        __syncthreads();
        const uint32_t stA = sbase + (c & 1) * STAGEB;
        const uint32_t stB = stA + TILEB;
#pragma unroll
        for (int k16 = 0; k16 < 2; ++k16) {
            uint32_t a[2][4], bb[16];
            ldsm4(a[0], stA + (wm      + a_row) * (RS*2) + k16*32 + a_colb);
            ldsm4(a[1], stA + (wm + 16 + a_row) * (RS*2) + k16*32 + a_colb);
#pragma unroll
            for (int p = 0; p < 4; ++p)
                ldsm4(&bb[4*p], stB + (wn + p*16 + b_row) * (RS*2) + k16*32 + b_colb);
#pragma unroll
            for (int mt = 0; mt < 2; ++mt)
#pragma unroll
                for (int nt = 0; nt < 8; ++nt)
                    mma_f16(acc[mt][nt], a[mt], &bb[nt*2]);
        }
        __syncthreads();
        if (c + 2 < NCH) load_stage(c + 2, c & 1);
    }

    const int er = lane >> 2;
    const int ec = (lane & 3) * 2;
#pragma unroll
    for (int mt = 0; mt < 2; ++mt) {
        const int row = m0 + wm + mt*16 + er;
#pragma unroll
        for (int nt = 0; nt < 8; ++nt) {
            const int col = n0 + wn + nt*8 + ec;
            const float b0 = bias[col], b1 = bias[col + 1];
            float v00 = (acc[mt][nt][0] + b0) * scale;
            float v01 = (acc[mt][nt][1] + b1) * scale;
            float v10 = (acc[mt][nt][2] + b0) * scale;
            float v11 = (acc[mt][nt][3] + b1) * scale;
            if (Ch) {
                *(uint32_t*)(Ch + (size_t)row * DM + col)       = packh2(v00, v01);
                *(uint32_t*)(Ch + (size_t)(row + 8) * DM + col) = packh2(v10, v11);
            } else {
                *(float2*)(Cf + (size_t)row * DM + col)       = make_float2(v00, v01);
                *(float2*)(Cf + (size_t)(row + 8) * DM + col) = make_float2(v10, v11);
            }
        }
    }
}

// ---------------------------------------------------------------------------
// fp16 flash attention (FA2-style):
//   grid (SL/128, NH*BSZ), 256 threads = 8 warps, warp owns 16 q-rows.
//   K tiles: [64][72] half, ldmatrix (non-trans) -> B-frags.
//   V tiles: [64][72] half, ldmatrix.x4.trans    -> B-frags.
//   P stays in registers: C-frag == A-frag layout for fp16 (no transpose!).
//   Double-buffered cp.async; 36.9 KB smem; 2 CTAs/SM.
// ---------------------------------------------------------------------------
#define SPH 72                        // halves per row (144 B)
#define KSTGB (64*SPH*2)              // 9216 B per stage
#define ATT_SMEM (4*KSTGB)            // K[2] + V[2] = 36864 B
#define NIT (SL/64)

__global__ __launch_bounds__(256, 2) void attn_f16_kernel(
    const __half* __restrict__ Qp, const __half* __restrict__ Kp,
    const __half* __restrict__ Vp, __half* __restrict__ Ao)
{
    extern __shared__ char asm_[];
    const uint32_t sb  = smem_u32(asm_);
    const uint32_t sbV = sb + 2*KSTGB;

    const int tid = threadIdx.x, wid = tid >> 5, lane = tid & 31;
    const int g = lane >> 2, tg = lane & 3;
    const int hb = blockIdx.y;
    const size_t base = (size_t)(hb & 1) * SL * DM + (size_t)(hb >> 1) * 64;
    const int q0 = blockIdx.x * 128;

    // ---- Q A-frags (fp16, already scaled by 0.125*log2e in projection) ----
    uint32_t aq[4][4];
    {
        const __half* Qr0 = Qp + base + (size_t)(q0 + wid*16 + g) * DM;
        const __half* Qr1 = Qr0 + (size_t)8 * DM;
#pragma unroll
        for (int kk = 0; kk < 4; ++kk) {
            aq[kk][0] = *(const uint32_t*)(Qr0 + kk*16 + 2*tg);
            aq[kk][1] = *(const uint32_t*)(Qr1 + kk*16 + 2*tg);
            aq[kk][2] = *(const uint32_t*)(Qr0 + kk*16 + 8 + 2*tg);
            aq[kk][3] = *(const uint32_t*)(Qr1 + kk*16 + 8 + 2*tg);
        }
    }

    // ---- KV loader: thread t -> row t/4, 32B (=16 halves) per array -------
    const int l_row = tid >> 2;
    const int l_cb  = (tid & 3) * 32;    // byte col
    auto loadKV = [&](int it, int s) {
        const __half* Kg = Kp + base + (size_t)(it*64 + l_row) * DM + l_cb/2;
        const __half* Vg = Vp + base + (size_t)(it*64 + l_row) * DM + l_cb/2;
        const uint32_t kd = sb  + s*KSTGB + l_row*(SPH*2) + l_cb;
        const uint32_t vd = sbV + s*KSTGB + l_row*(SPH*2) + l_cb;
        cpa16(kd,      Kg);
        cpa16(kd + 16, Kg + 8);
        cpa16(vd,      Vg);
        cpa16(vd + 16, Vg + 8);
        asm volatile("cp.async.commit_group;" ::: "memory");
    };

    float acc[8][4];
#pragma unroll
    for (int j = 0; j < 8; ++j)
#pragma unroll
        for (int i = 0; i < 4; ++i) acc[j][i] = 0.f;
    float m0 = -INFINITY, m1 = -INFINITY, l0 = 0.f, l1 = 0.f;

    loadKV(0, 0);
    loadKV(1, 1);

    const int b_row  = ((lane & 16) ? 8 : 0) + (lane & 7);
    const int b_colb = (lane & 8) ? 16 : 0;
    const int v_rowo = ((lane & 8) ? 8 : 0) + (lane & 7);
    const int v_colb = (lane & 16) ? 16 : 0;

    for (int it = 0; it < NIT; ++it) {
        const int s = it & 1;
        if (it < NIT - 1) asm volatile("cp.async.wait_group 1;" ::: "memory");
        else              asm volatile("cp.async.wait_group 0;" ::: "memory");
        __syncthreads();
        const uint32_t Kt = sb  + s*KSTGB;
        const uint32_t Vt = sbV + s*KSTGB;

        // ---- S = Q @ K^T (64 cols), fp32 accum ----
        float sc[8][4];
#pragma unroll
        for (int j = 0; j < 8; ++j)
#pragma unroll
            for (int i = 0; i < 4; ++i) sc[j][i] = 0.f;
#pragma unroll
        for (int kk = 0; kk < 4; ++kk) {
#pragma unroll
            for (int p = 0; p < 4; ++p) {
                uint32_t bk[4];
                ldsm4(bk, Kt + (p*16 + b_row) * (SPH*2) + kk*32 + b_colb);
                mma_f16(sc[2*p],     aq[kk], bk);
                mma_f16(sc[2*p + 1], aq[kk], bk + 2);
            }
        }

        // ---- online softmax (base-2; Q pre-scaled by log2e/8) ----
        float mx0 = -INFINITY, mx1 = -INFINITY;
#pragma unroll
        for (int j = 0; j < 8; ++j) {
            mx0 = fmaxf(mx0, fmaxf(sc[j][0], sc[j][1]));
            mx1 = fmaxf(mx1, fmaxf(sc[j][2], sc[j][3]));
        }
        mx0 = fmaxf(mx0, __shfl_xor_sync(0xffffffffu, mx0, 1));
        mx0 = fmaxf(mx0, __shfl_xor_sync(0xffffffffu, mx0, 2));
        mx1 = fmaxf(mx1, __shfl_xor_sync(0xffffffffu, mx1, 1));
        mx1 = fmaxf(mx1, __shfl_xor_sync(0xffffffffu, mx1, 2));

        const float mn0 = fmaxf(m0, mx0), mn1 = fmaxf(m1, mx1);
        const float c0 = exp2f(m0 - mn0), c1 = exp2f(m1 - mn1);
        m0 = mn0; m1 = mn1;
        float rs0 = 0.f, rs1 = 0.f;
#pragma unroll
        for (int j = 0; j < 8; ++j) {
            sc[j][0] = exp2f(sc[j][0] - mn0);
            sc[j][1] = exp2f(sc[j][1] - mn0);
            sc[j][2] = exp2f(sc[j][2] - mn1);
            sc[j][3] = exp2f(sc[j][3] - mn1);
            rs0 += sc[j][0] + sc[j][1];
            rs1 += sc[j][2] + sc[j][3];
        }
        rs0 += __shfl_xor_sync(0xffffffffu, rs0, 1);
        rs0 += __shfl_xor_sync(0xffffffffu, rs0, 2);
        rs1 += __shfl_xor_sync(0xffffffffu, rs1, 1);
        rs1 += __shfl_xor_sync(0xffffffffu, rs1, 2);
        l0 = l0 * c0 + rs0;
        l1 = l1 * c1 + rs1;
#pragma unroll
        for (int j = 0; j < 8; ++j) {
            acc[j][0] *= c0; acc[j][1] *= c0;
            acc[j][2] *= c1; acc[j][3] *= c1;
        }

        // ---- O += P @ V : P C-frags pack directly into fp16 A-frags -------
#pragma unroll
        for (int kk = 0; kk < 4; ++kk) {
            uint32_t ap[4];
            ap[0] = packh2(sc[2*kk][0],     sc[2*kk][1]);
            ap[1] = packh2(sc[2*kk][2],     sc[2*kk][3]);
            ap[2] = packh2(sc[2*kk + 1][0], sc[2*kk + 1][1]);
            ap[3] = packh2(sc[2*kk + 1][2], sc[2*kk + 1][3]);
#pragma unroll
            for (int jp = 0; jp < 4; ++jp) {
                uint32_t bv[4];
                ldsm4t(bv, Vt + (kk*16 + v_rowo) * (SPH*2) + jp*32 + v_colb);
                mma_f16(acc[2*jp],     ap, bv);
                mma_f16(acc[2*jp + 1], ap, bv + 2);
            }
        }

        __syncthreads();
        if (it + 2 < NIT) loadKV(it + 2, s);
    }

    // ---- epilogue: normalize, write half ----
    const float i0 = 1.f / l0, i1 = 1.f / l1;
    const size_t ro0 = base + (size_t)(q0 + wid*16 + g) * DM;
    const size_t ro1 = ro0 + (size_t)8 * DM;
#pragma unroll
    for (int j = 0; j < 8; ++j) {
        const int col = 8*j + 2*tg;
        *(uint32_t*)(Ao + ro0 + col) = packh2(acc[j][0] * i0, acc[j][1] * i0);
        *(uint32_t*)(Ao + ro1 + col) = packh2(acc[j][2] * i1, acc[j][3] * i1);
    }
}

// ---------------------------------------------------------------------------
extern "C" void kernel_launch(void* const* d_in, const int* in_sizes, int n_in,
                              void* d_out, int out_size)
{
    const float* q   = (const float*)d_in[0];
    const float* k   = (const float*)d_in[1];
    const float* v   = (const float*)d_in[2];
    const float* w_q = (const float*)d_in[3];
    const float* b_q = (const float*)d_in[4];
    const float* w_k = (const float*)d_in[5];
    const float* b_k = (const float*)d_in[6];
    const float* w_v = (const float*)d_in[7];
    const float* b_v = (const float*)d_in[8];
    const float* w_o = (const float*)d_in[9];
    const float* b_o = (const float*)d_in[10];
    float* out = (float*)d_out;

    cudaFuncSetAttribute(gemm_f16_kernel,
                         cudaFuncAttributeMaxDynamicSharedMemorySize, GEMM_SMEM);
    cudaFuncSetAttribute(attn_f16_kernel,
                         cudaFuncAttributeMaxDynamicSharedMemorySize, ATT_SMEM);

    __half *pq, *pk, *pv, *pao, *iq, *ik, *iv;
    __half *wq, *wk, *wv, *wo;
    cudaGetSymbolAddress((void**)&pq,  h_q);
    cudaGetSymbolAddress((void**)&pk,  h_k);
    cudaGetSymbolAddress((void**)&pv,  h_v);
    cudaGetSymbolAddress((void**)&pao, h_ao);
    cudaGetSymbolAddress((void**)&iq,  h_qi);
    cudaGetSymbolAddress((void**)&ik,  h_ki);
    cudaGetSymbolAddress((void**)&iv,  h_vi);
    cudaGetSymbolAddress((void**)&wq,  h_wq);
    cudaGetSymbolAddress((void**)&wk,  h_wk);
    cudaGetSymbolAddress((void**)&wv,  h_wv);
    cudaGetSymbolAddress((void**)&wo,  h_wo);

    const int n4 = MR * DM / 4;
    const dim3 cgrid((n4 + 255) / 256), cblk(256);
    tohalf_kernel<<<cgrid, cblk>>>((const float4*)q, (uint2*)iq, n4);
    tohalf_kernel<<<cgrid, cblk>>>((const float4*)k, (uint2*)ik, n4);
    tohalf_kernel<<<cgrid, cblk>>>((const float4*)v, (uint2*)iv, n4);

    const dim3 tgrid(DM/32, DM/32), tblk(32, 8);
    trth_kernel<<<tgrid, tblk>>>(w_q, wq);
    trth_kernel<<<tgrid, tblk>>>(w_k, wk);
    trth_kernel<<<tgrid, tblk>>>(w_v, wv);
    trth_kernel<<<tgrid, tblk>>>(w_o, wo);

    const float QSC = 0.125f * 1.4426950408889634f;   // 1/sqrt(dk) * log2(e)
    const dim3 ggrid(MR/128, DM/128);                 // (32, 8)
    gemm_f16_kernel<<<ggrid, 256, GEMM_SMEM>>>(iq, wq, b_q, pq, nullptr, QSC);
    gemm_f16_kernel<<<ggrid, 256, GEMM_SMEM>>>(ik, wk, b_k, pk, nullptr, 1.0f);
    gemm_f16_kernel<<<ggrid, 256, GEMM_SMEM>>>(iv, wv, b_v, pv, nullptr, 1.0f);

    attn_f16_kernel<<<dim3(SL/128, NH*BSZ), 256, ATT_SMEM>>>(pq, pk, pv, pao);

    gemm_f16_kernel<<<ggrid, 256, GEMM_SMEM>>>(pao, wo, b_o, nullptr, out, 1.0f);
}

// round 10
// speedup vs baseline: 6.5012x; 1.0919x over previous
#include <cuda_runtime.h>
#include <cuda_fp16.h>
#include <math.h>
#include <stdint.h>

#define DM 1024
#define BSZ 2
#define SL  2048
#define NH  16
#define MR  (BSZ*SL)

// ---------------------------------------------------------------------------
// Scratch (device globals: allocation-free per harness rules)
// ---------------------------------------------------------------------------
__device__ __half h_q [MR*DM];    // projected Q (pre-scaled by 0.125*log2e)
__device__ __half h_k [MR*DM];
__device__ __half h_v [MR*DM];
__device__ __half h_ao[MR*DM];    // attention output
__device__ __half h_qi[MR*DM];    // fp16-converted raw inputs
__device__ __half h_ki[MR*DM];
__device__ __half h_vi[MR*DM];
__device__ __half h_wq[DM*DM];    // transposed fp16 weights [n][k]
__device__ __half h_wk[DM*DM];
__device__ __half h_wv[DM*DM];
__device__ __half h_wo[DM*DM];

// ---------------------------------------------------------------------------
// Helpers (family-portable PTX: cp.async, ldmatrix, mma.sync)
// ---------------------------------------------------------------------------
__device__ __forceinline__ uint32_t smem_u32(const void* p) {
    uint32_t a;
    asm("{ .reg .u64 t; cvta.to.shared.u64 t, %1; cvt.u32.u64 %0, t; }"
        : "=r"(a) : "l"(p));
    return a;
}
__device__ __forceinline__ void cpa16(uint32_t dst, const void* src) {
    asm volatile("cp.async.cg.shared.global [%0], [%1], 16;" :: "r"(dst), "l"(src));
}
__device__ __forceinline__ void ldsm4(uint32_t* r, uint32_t addr) {
    asm volatile("ldmatrix.sync.aligned.m8n8.x4.shared.b16 {%0,%1,%2,%3}, [%4];"
        : "=r"(r[0]), "=r"(r[1]), "=r"(r[2]), "=r"(r[3]) : "r"(addr));
}
__device__ __forceinline__ void ldsm4t(uint32_t* r, uint32_t addr) {
    asm volatile("ldmatrix.sync.aligned.m8n8.x4.trans.shared.b16 {%0,%1,%2,%3}, [%4];"
        : "=r"(r[0]), "=r"(r[1]), "=r"(r[2]), "=r"(r[3]) : "r"(addr));
}
__device__ __forceinline__ void mma_f16(float* c, const uint32_t* a, const uint32_t* b) {
    asm volatile("mma.sync.aligned.m16n8k16.row.col.f32.f16.f16.f32 "
        "{%0,%1,%2,%3}, {%4,%5,%6,%7}, {%8,%9}, {%0,%1,%2,%3};"
        : "+f"(c[0]), "+f"(c[1]), "+f"(c[2]), "+f"(c[3])
        : "r"(a[0]), "r"(a[1]), "r"(a[2]), "r"(a[3]), "r"(b[0]), "r"(b[1]));
}
__device__ __forceinline__ uint32_t packh2(float a, float b) {
    __half2 h = __float22half2_rn(make_float2(a, b));
    return *(uint32_t*)&h;
}

// ---------------------------------------------------------------------------
// Merged fp32 -> fp16 conversion for q,k,v (one launch)
// ---------------------------------------------------------------------------
__global__ void tohalf3_kernel(const float4* __restrict__ x0,
                               const float4* __restrict__ x1,
                               const float4* __restrict__ x2,
                               uint2* __restrict__ y0, uint2* __restrict__ y1,
                               uint2* __restrict__ y2, int n4)
{
    int i = blockIdx.x * blockDim.x + threadIdx.x;
    const float4* x; uint2* y; int j = i;
    if (j < n4)            { x = x0; y = y0; }
    else if (j < 2*n4)     { x = x1; y = y1; j -= n4; }
    else if (j < 3*n4)     { x = x2; y = y2; j -= 2*n4; }
    else return;
    float4 v = x[j];
    uint2 u;
    u.x = packh2(v.x, v.y);
    u.y = packh2(v.z, v.w);
    y[j] = u;
}

// Merged transpose+fp16 for all 4 weights (grid.z selects)
__global__ void trth4_kernel(const float* __restrict__ W0, const float* __restrict__ W1,
                             const float* __restrict__ W2, const float* __restrict__ W3,
                             __half* __restrict__ T0, __half* __restrict__ T1,
                             __half* __restrict__ T2, __half* __restrict__ T3)
{
    const float* W; __half* WT;
    switch (blockIdx.z) {
        case 0: W = W0; WT = T0; break;
        case 1: W = W1; WT = T1; break;
        case 2: W = W2; WT = T2; break;
        default: W = W3; WT = T3; break;
    }
    __shared__ float t[32][33];
    const int tx = threadIdx.x, ty = threadIdx.y;   // 32 x 8
    const int n0 = blockIdx.x * 32, k0 = blockIdx.y * 32;
#pragma unroll
    for (int r = 0; r < 4; ++r)
        t[ty + 8*r][tx] = W[(k0 + ty + 8*r) * DM + n0 + tx];
    __syncthreads();
#pragma unroll
    for (int r = 0; r < 4; ++r)
        WT[(n0 + ty + 8*r) * DM + k0 + tx] = __float2half_rn(t[tx][ty + 8*r]);
}

// ---------------------------------------------------------------------------
// fp16 mma.sync GEMM, 3-stage cp.async pipeline, one barrier per chunk.
//   Block 128x128, BK=32, 256 threads (8 warps 4m x 2n), warp tile 32x64.
//   2 CTAs/SM via launch_bounds(256,2). 61.4 KB smem.
// ---------------------------------------------------------------------------
#define RS 40                       // halves per smem row (80 B)
#define TILEB (128*RS*2)            // 10240 B
#define STAGEB (2*TILEB)            // A + B = 20480 B
#define GEMM_SMEM (3*STAGEB)        // 61440 B
#define NCH (DM/32)                 // 32

__global__ __launch_bounds__(256, 2) void gemm_f16_kernel(
    const __half* __restrict__ A, const __half* __restrict__ BT,
    const float* __restrict__ bias, __half* __restrict__ Ch,
    float* __restrict__ Cf, float scale)
{
    extern __shared__ char smem[];
    const uint32_t sbase = smem_u32(smem);
    const int tid  = threadIdx.x;
    const int wid  = tid >> 5;
    const int lane = tid & 31;
    const int m0 = blockIdx.x * 128;
    const int n0 = blockIdx.y * 128;
    const int wm = (wid >> 1) * 32;
    const int wn = (wid & 1) * 64;

    const int lrow = tid >> 1;
    const int lk0  = (tid & 1) * 16;
    const size_t gA = (size_t)(m0 + lrow) * DM;
    const size_t gB = (size_t)(n0 + lrow) * DM;

    auto load_stage = [&](int c, int s) {
        const uint32_t stA = sbase + s * STAGEB;
        const uint32_t stB = stA + TILEB;
        const int k0 = c * 32 + lk0;
        const uint32_t so = lrow * (RS*2) + lk0 * 2;
        cpa16(stA + so,      A  + gA + k0);
        cpa16(stA + so + 16, A  + gA + k0 + 8);
        cpa16(stB + so,      BT + gB + k0);
        cpa16(stB + so + 16, BT + gB + k0 + 8);
        asm volatile("cp.async.commit_group;" ::: "memory");
    };

    float acc[2][8][4];
#pragma unroll
    for (int mt = 0; mt < 2; ++mt)
#pragma unroll
        for (int nt = 0; nt < 8; ++nt)
#pragma unroll
            for (int j = 0; j < 4; ++j) acc[mt][nt][j] = 0.f;

    load_stage(0, 0);
    load_stage(1, 1);

    const int a_row  = (lane & 15);
    const int a_colb = (lane & 16) ? 16 : 0;
    const int b_row  = ((lane & 16) ? 8 : 0) + (lane & 7);
    const int b_colb = (lane & 8) ? 16 : 0;

    int s = 0;
    for (int c = 0; c < NCH; ++c) {
        if (c < NCH - 1) asm volatile("cp.async.wait_group 1;" ::: "memory");
        else             asm volatile("cp.async.wait_group 0;" ::: "memory");
        __syncthreads();
        if (c + 2 < NCH) {
            int s2 = s + 2; if (s2 >= 3) s2 -= 3;
            load_stage(c + 2, s2);
        }
        const uint32_t stA = sbase + s * STAGEB;
        const uint32_t stB = stA + TILEB;
#pragma unroll
        for (int k16 = 0; k16 < 2; ++k16) {
            uint32_t a[2][4], bb[16];
            ldsm4(a[0], stA + (wm      + a_row) * (RS*2) + k16*32 + a_colb);
            ldsm4(a[1], stA + (wm + 16 + a_row) * (RS*2) + k16*32 + a_colb);
#pragma unroll
            for (int p = 0; p < 4; ++p)
                ldsm4(&bb[4*p], stB + (wn + p*16 + b_row) * (RS*2) + k16*32 + b_colb);
#pragma unroll
            for (int mt = 0; mt < 2; ++mt)
#pragma unroll
                for (int nt = 0; nt < 8; ++nt)
                    mma_f16(acc[mt][nt], a[mt], &bb[nt*2]);
        }
        if (++s >= 3) s -= 3;
    }

    const int er = lane >> 2;
    const int ec = (lane & 3) * 2;
#pragma unroll
    for (int mt = 0; mt < 2; ++mt) {
        const int row = m0 + wm + mt*16 + er;
#pragma unroll
        for (int nt = 0; nt < 8; ++nt) {
            const int col = n0 + wn + nt*8 + ec;
            const float b0 = bias[col], b1 = bias[col + 1];
            float v00 = (acc[mt][nt][0] + b0) * scale;
            float v01 = (acc[mt][nt][1] + b1) * scale;
            float v10 = (acc[mt][nt][2] + b0) * scale;
            float v11 = (acc[mt][nt][3] + b1) * scale;
            if (Ch) {
                *(uint32_t*)(Ch + (size_t)row * DM + col)       = packh2(v00, v01);
                *(uint32_t*)(Ch + (size_t)(row + 8) * DM + col) = packh2(v10, v11);
            } else {
                *(float2*)(Cf + (size_t)row * DM + col)       = make_float2(v00, v01);
                *(float2*)(Cf + (size_t)(row + 8) * DM + col) = make_float2(v10, v11);
            }
        }
    }
}

// ---------------------------------------------------------------------------
// fp16 flash attention, 3-stage KV pipeline, one barrier per iter,
// row-sum via ones-MMA (no shuffle reduction for l).
// ---------------------------------------------------------------------------
#define SPH 72                        // halves per row (144 B)
#define KSTGB (64*SPH*2)              // 9216 B per tile per stage
#define ATT_SMEM (6*KSTGB)            // K[3] + V[3] = 55296 B
#define NIT (SL/64)

__global__ __launch_bounds__(256, 2) void attn_f16_kernel(
    const __half* __restrict__ Qp, const __half* __restrict__ Kp,
    const __half* __restrict__ Vp, __half* __restrict__ Ao)
{
    extern __shared__ char asm_[];
    const uint32_t sb  = smem_u32(asm_);
    const uint32_t sbV = sb + 3*KSTGB;

    const int tid = threadIdx.x, wid = tid >> 5, lane = tid & 31;
    const int g = lane >> 2, tg = lane & 3;
    const int hb = blockIdx.y;
    const size_t base = (size_t)(hb & 1) * SL * DM + (size_t)(hb >> 1) * 64;
    const int q0 = blockIdx.x * 128;

    // ---- Q A-frags (fp16, pre-scaled by 0.125*log2e in projection) ----
    uint32_t aq[4][4];
    {
        const __half* Qr0 = Qp + base + (size_t)(q0 + wid*16 + g) * DM;
        const __half* Qr1 = Qr0 + (size_t)8 * DM;
#pragma unroll
        for (int kk = 0; kk < 4; ++kk) {
            aq[kk][0] = *(const uint32_t*)(Qr0 + kk*16 + 2*tg);
            aq[kk][1] = *(const uint32_t*)(Qr1 + kk*16 + 2*tg);
            aq[kk][2] = *(const uint32_t*)(Qr0 + kk*16 + 8 + 2*tg);
            aq[kk][3] = *(const uint32_t*)(Qr1 + kk*16 + 8 + 2*tg);
        }
    }

    const int l_row = tid >> 2;
    const int l_cb  = (tid & 3) * 32;
    auto loadKV = [&](int it, int s) {
        const __half* Kg = Kp + base + (size_t)(it*64 + l_row) * DM + l_cb/2;
        const __half* Vg = Vp + base + (size_t)(it*64 + l_row) * DM + l_cb/2;
        const uint32_t kd = sb  + s*KSTGB + l_row*(SPH*2) + l_cb;
        const uint32_t vd = sbV + s*KSTGB + l_row*(SPH*2) + l_cb;
        cpa16(kd,      Kg);
        cpa16(kd + 16, Kg + 8);
        cpa16(vd,      Vg);
        cpa16(vd + 16, Vg + 8);
        asm volatile("cp.async.commit_group;" ::: "memory");
    };

    float acc[8][4];
#pragma unroll
    for (int j = 0; j < 8; ++j)
#pragma unroll
        for (int i = 0; i < 4; ++i) acc[j][i] = 0.f;
    float m0 = -INFINITY, m1 = -INFINITY, l0 = 0.f, l1 = 0.f;

    loadKV(0, 0);
    loadKV(1, 1);

    const int b_row  = ((lane & 16) ? 8 : 0) + (lane & 7);
    const int b_colb = (lane & 8) ? 16 : 0;
    const int v_rowo = ((lane & 8) ? 8 : 0) + (lane & 7);
    const int v_colb = (lane & 16) ? 16 : 0;
    const uint32_t ONE2 = 0x3C003C00u;          // half2(1.0, 1.0)
    const uint32_t bones[2] = { ONE2, ONE2 };

    int s = 0;
    for (int it = 0; it < NIT; ++it) {
        if (it < NIT - 1) asm volatile("cp.async.wait_group 1;" ::: "memory");
        else              asm volatile("cp.async.wait_group 0;" ::: "memory");
        __syncthreads();
        if (it + 2 < NIT) {
            int s2 = s + 2; if (s2 >= 3) s2 -= 3;
            loadKV(it + 2, s2);
        }
        const uint32_t Kt = sb  + s*KSTGB;
        const uint32_t Vt = sbV + s*KSTGB;

        // ---- S = Q @ K^T (64 cols), fp32 accum ----
        float sc[8][4];
#pragma unroll
        for (int j = 0; j < 8; ++j)
#pragma unroll
            for (int i = 0; i < 4; ++i) sc[j][i] = 0.f;
#pragma unroll
        for (int kk = 0; kk < 4; ++kk) {
#pragma unroll
            for (int p = 0; p < 4; ++p) {
                uint32_t bk[4];
                ldsm4(bk, Kt + (p*16 + b_row) * (SPH*2) + kk*32 + b_colb);
                mma_f16(sc[2*p],     aq[kk], bk);
                mma_f16(sc[2*p + 1], aq[kk], bk + 2);
            }
        }

        // ---- online softmax (base-2) ----
        float mx0 = -INFINITY, mx1 = -INFINITY;
#pragma unroll
        for (int j = 0; j < 8; ++j) {
            mx0 = fmaxf(mx0, fmaxf(sc[j][0], sc[j][1]));
            mx1 = fmaxf(mx1, fmaxf(sc[j][2], sc[j][3]));
        }
        mx0 = fmaxf(mx0, __shfl_xor_sync(0xffffffffu, mx0, 1));
        mx0 = fmaxf(mx0, __shfl_xor_sync(0xffffffffu, mx0, 2));
        mx1 = fmaxf(mx1, __shfl_xor_sync(0xffffffffu, mx1, 1));
        mx1 = fmaxf(mx1, __shfl_xor_sync(0xffffffffu, mx1, 2));

        const float mn0 = fmaxf(m0, mx0), mn1 = fmaxf(m1, mx1);
        const float c0 = exp2f(m0 - mn0), c1 = exp2f(m1 - mn1);
        m0 = mn0; m1 = mn1;
#pragma unroll
        for (int j = 0; j < 8; ++j) {
            sc[j][0] = exp2f(sc[j][0] - mn0);
            sc[j][1] = exp2f(sc[j][1] - mn0);
            sc[j][2] = exp2f(sc[j][2] - mn1);
            sc[j][3] = exp2f(sc[j][3] - mn1);
        }
#pragma unroll
        for (int j = 0; j < 8; ++j) {
            acc[j][0] *= c0; acc[j][1] *= c0;
            acc[j][2] *= c1; acc[j][3] *= c1;
        }

        // ---- O += P @ V; l += P @ 1 (ones-MMA, fp32-exact row sums) -------
        float lacc[4] = {0.f, 0.f, 0.f, 0.f};
#pragma unroll
        for (int kk = 0; kk < 4; ++kk) {
            uint32_t ap[4];
            ap[0] = packh2(sc[2*kk][0],     sc[2*kk][1]);
            ap[1] = packh2(sc[2*kk][2],     sc[2*kk][3]);
            ap[2] = packh2(sc[2*kk + 1][0], sc[2*kk + 1][1]);
            ap[3] = packh2(sc[2*kk + 1][2], sc[2*kk + 1][3]);
            mma_f16(lacc, ap, bones);
#pragma unroll
            for (int jp = 0; jp < 4; ++jp) {
                uint32_t bv[4];
                ldsm4t(bv, Vt + (kk*16 + v_rowo) * (SPH*2) + jp*32 + v_colb);
                mma_f16(acc[2*jp],     ap, bv);
                mma_f16(acc[2*jp + 1], ap, bv + 2);
            }
        }
        l0 = l0 * c0 + lacc[0];
        l1 = l1 * c1 + lacc[2];

        if (++s >= 3) s -= 3;
    }

    // ---- epilogue: normalize, write half ----
    const float i0 = 1.f / l0, i1 = 1.f / l1;
    const size_t ro0 = base + (size_t)(q0 + wid*16 + g) * DM;
    const size_t ro1 = ro0 + (size_t)8 * DM;
#pragma unroll
    for (int j = 0; j < 8; ++j) {
        const int col = 8*j + 2*tg;
        *(uint32_t*)(Ao + ro0 + col) = packh2(acc[j][0] * i0, acc[j][1] * i0);
        *(uint32_t*)(Ao + ro1 + col) = packh2(acc[j][2] * i1, acc[j][3] * i1);
    }
}

// ---------------------------------------------------------------------------
extern "C" void kernel_launch(void* const* d_in, const int* in_sizes, int n_in,
                              void* d_out, int out_size)
{
    const float* q   = (const float*)d_in[0];
    const float* k   = (const float*)d_in[1];
    const float* v   = (const float*)d_in[2];
    const float* w_q = (const float*)d_in[3];
    const float* b_q = (const float*)d_in[4];
    const float* w_k = (const float*)d_in[5];
    const float* b_k = (const float*)d_in[6];
    const float* w_v = (const float*)d_in[7];
    const float* b_v = (const float*)d_in[8];
    const float* w_o = (const float*)d_in[9];
    const float* b_o = (const float*)d_in[10];
    float* out = (float*)d_out;

    cudaFuncSetAttribute(gemm_f16_kernel,
                         cudaFuncAttributeMaxDynamicSharedMemorySize, GEMM_SMEM);
    cudaFuncSetAttribute(attn_f16_kernel,
                         cudaFuncAttributeMaxDynamicSharedMemorySize, ATT_SMEM);

    __half *pq, *pk, *pv, *pao, *iq, *ik, *iv;
    __half *wq, *wk, *wv, *wo;
    cudaGetSymbolAddress((void**)&pq,  h_q);
    cudaGetSymbolAddress((void**)&pk,  h_k);
    cudaGetSymbolAddress((void**)&pv,  h_v);
    cudaGetSymbolAddress((void**)&pao, h_ao);
    cudaGetSymbolAddress((void**)&iq,  h_qi);
    cudaGetSymbolAddress((void**)&ik,  h_ki);
    cudaGetSymbolAddress((void**)&iv,  h_vi);
    cudaGetSymbolAddress((void**)&wq,  h_wq);
    cudaGetSymbolAddress((void**)&wk,  h_wk);
    cudaGetSymbolAddress((void**)&wv,  h_wv);
    cudaGetSymbolAddress((void**)&wo,  h_wo);

    const int n4 = MR * DM / 4;
    tohalf3_kernel<<<(3*n4 + 255) / 256, 256>>>(
        (const float4*)q, (const float4*)k, (const float4*)v,
        (uint2*)iq, (uint2*)ik, (uint2*)iv, n4);

    trth4_kernel<<<dim3(DM/32, DM/32, 4), dim3(32, 8)>>>(
        w_q, w_k, w_v, w_o, wq, wk, wv, wo);

    const float QSC = 0.125f * 1.4426950408889634f;   // 1/sqrt(dk) * log2(e)
    const dim3 ggrid(MR/128, DM/128);                 // (32, 8)
    gemm_f16_kernel<<<ggrid, 256, GEMM_SMEM>>>(iq, wq, b_q, pq, nullptr, QSC);
    gemm_f16_kernel<<<ggrid, 256, GEMM_SMEM>>>(ik, wk, b_k, pk, nullptr, 1.0f);
    gemm_f16_kernel<<<ggrid, 256, GEMM_SMEM>>>(iv, wv, b_v, pv, nullptr, 1.0f);

    attn_f16_kernel<<<dim3(SL/128, NH*BSZ), 256, ATT_SMEM>>>(pq, pk, pv, pao);

    gemm_f16_kernel<<<ggrid, 256, GEMM_SMEM>>>(pao, wo, b_o, nullptr, out, 1.0f);
}